// round 10
// baseline (speedup 1.0000x reference)
#include <cuda_runtime.h>
#include <cuda.h>
#include <cuda_fp16.h>
#include <math.h>
#include <stdint.h>

#define T_TOK 8192
#define D_DIM 1024
#define H_DIM 2048
#define E_EXP 4
#define DP_H  512

// ---------------- scratch (device globals; no allocations) -------------------
__device__ __half g_xh  [(size_t)T_TOK * D_DIM];           // x hi (fp16)
__device__ __half g_xlo [(size_t)T_TOK * D_DIM];           // x lo (fp16)
__device__ __half g_hidh[(size_t)E_EXP * T_TOK * H_DIM];   // expert hidden fp16
__device__ float  g_y   [(size_t)E_EXP * T_TOK * D_DIM];   // expert outputs
__device__ __half g_w1t [(size_t)E_EXP * D_DIM * H_DIM];   // [E][H][D] K-contig fp16
__device__ __half g_w2t [(size_t)E_EXP * H_DIM * D_DIM];   // [E][D][H] K-contig fp16
__device__ __half g_dwhi[(size_t)DP_H * D_DIM];            // dp_w1^T hi [512][1024]
__device__ __half g_dwlo[(size_t)DP_H * D_DIM];            // dp_w1^T lo
__device__ float  g_entp[4][T_TOK];                        // dp entropy partials
__device__ float  g_dw  [(size_t)T_TOK * E_EXP];
__device__ int    g_cnt [E_EXP];
__device__ int    g_list[(size_t)E_EXP * T_TOK];

// ---------------- helpers ----------------------------------------------------
__device__ __forceinline__ uint32_t smem_to_u32(const void* p) {
    uint32_t a;
    asm("{ .reg .u64 t; cvta.to.shared.u64 t, %1; cvt.u32.u64 %0, t; }" : "=r"(a) : "l"(p));
    return a;
}

#define CPA16(dst, src) \
    asm volatile("cp.async.cg.shared.global [%0], [%1], 16;" :: "r"(dst), "l"(src) : "memory")
#define CPA_COMMIT() asm volatile("cp.async.commit_group;" ::: "memory")
#define CPA_WAIT1()  asm volatile("cp.async.wait_group 1;" ::: "memory")

#define LDSM_X4(r, addr) \
    asm volatile("ldmatrix.sync.aligned.m8n8.x4.shared.b16 {%0,%1,%2,%3}, [%4];" \
        : "=r"((r)[0]), "=r"((r)[1]), "=r"((r)[2]), "=r"((r)[3]) : "r"(addr))

#define MMA_F16(c, a0, a1, a2, a3, b0, b1) \
    asm volatile("mma.sync.aligned.m16n8k16.row.col.f32.f16.f16.f32 " \
        "{%0,%1,%2,%3}, {%4,%5,%6,%7}, {%8,%9}, {%0,%1,%2,%3};" \
        : "+f"((c)[0]), "+f"((c)[1]), "+f"((c)[2]), "+f"((c)[3]) \
        : "r"(a0), "r"(a1), "r"(a2), "r"(a3), "r"(b0), "r"(b1))

// ---------------- init -------------------------------------------------------
__global__ void init_kernel() {
    if (threadIdx.x < E_EXP) g_cnt[threadIdx.x] = 0;
}

// ---------------- x -> fp16 hi + lo ------------------------------------------
__global__ void xsplit_k(const float* __restrict__ in,
                         __half* __restrict__ hi, __half* __restrict__ lo) {
    size_t i = (size_t)blockIdx.x * blockDim.x + threadIdx.x;
    float4 v = ((const float4*)in)[i];
    __half2 h0 = __floats2half2_rn(v.x, v.y);
    __half2 h1 = __floats2half2_rn(v.z, v.w);
    __half2 l0 = __floats2half2_rn(v.x - __low2float(h0), v.y - __high2float(h0));
    __half2 l1 = __floats2half2_rn(v.z - __low2float(h1), v.w - __high2float(h1));
    __half2 hh[2] = { h0, h1 };
    __half2 ll[2] = { l0, l1 };
    ((uint2*)hi)[i] = *(uint2*)hh;
    ((uint2*)lo)[i] = *(uint2*)ll;
}

// ---------------- transpose: in [z][R][C] f32 -> out [z][C][R] fp16 ----------
// (known-good scalar version from R7)
__global__ void transpose_k(const float* __restrict__ in, __half* __restrict__ out,
                            int R, int C) {
    __shared__ float t[32][33];
    int z = blockIdx.z;
    const float* I = in + (size_t)z * R * C;
    __half* O = out + (size_t)z * R * C;
    int r0 = blockIdx.y * 32, c0 = blockIdx.x * 32;
    int tx = threadIdx.x, ty = threadIdx.y;  // 32 x 8
#pragma unroll
    for (int i = 0; i < 32; i += 8)
        t[ty + i][tx] = I[(size_t)(r0 + ty + i) * C + c0 + tx];
    __syncthreads();
#pragma unroll
    for (int i = 0; i < 32; i += 8)
        O[(size_t)(c0 + ty + i) * R + r0 + tx] = __float2half_rn(t[tx][ty + i]);
}

// ---------------- transpose with hi/lo split: [R][C] f32 -> [C][R] fp16 x2 ---
// (known-good scalar version from R7)
__global__ void transpose_hl_k(const float* __restrict__ in,
                               __half* __restrict__ ohi, __half* __restrict__ olo,
                               int R, int C) {
    __shared__ float t[32][33];
    int r0 = blockIdx.y * 32, c0 = blockIdx.x * 32;
    int tx = threadIdx.x, ty = threadIdx.y;  // 32 x 8
#pragma unroll
    for (int i = 0; i < 32; i += 8)
        t[ty + i][tx] = in[(size_t)(r0 + ty + i) * C + c0 + tx];
    __syncthreads();
#pragma unroll
    for (int i = 0; i < 32; i += 8) {
        float v = t[tx][ty + i];
        __half h = __float2half_rn(v);
        __half l = __float2half_rn(v - __half2float(h));
        ohi[(size_t)(c0 + ty + i) * R + r0 + tx] = h;
        olo[(size_t)(c0 + ty + i) * R + r0 + tx] = l;
    }
}

// ---------------- tensor-core fp16x3 dp GEMM + fused entropy (512 thr) -------
// h = relu(X @ W1^T + b1), 3-term split; g_entp[by][t] = sum h*w2 over 128-col
// slab. Block 128x128xk32, 16 warps (4m x 4n), warp tile 32x32, 3 stages.
#define DP_STR  10240              /* one 128x(32h) stream, 80B rows */
#define DP_STAGE (4 * DP_STR)
#define DP_TOTAL (1024 + 3 * DP_STAGE)

__global__ __launch_bounds__(512, 1)
void dptc_k(const __half* __restrict__ Ahi, const __half* __restrict__ Alo,
            const __half* __restrict__ Bhi, const __half* __restrict__ Blo,
            const float* __restrict__ bias, const float* __restrict__ w2)
{
    extern __shared__ __align__(128) char smem[];
    const int m0 = blockIdx.x * 128;
    const int n0 = blockIdx.y * 128;
    const uint32_t sbase = smem_to_u32(smem) + 1024;
    const int tid = threadIdx.x;
    const int lane = tid & 31;
    const int wid = tid >> 5;
    const int wm = wid & 3;       // 4 warps in m (32 rows)
    const int wn = wid >> 2;      // 4 warps in n (32 cols)
    const int K = D_DIM;

    // cp.async: thread covers stream (tid>>7), row (tid&127), 4x16B chunks
    const int strm = tid >> 7;
    const int row = tid & 127;
    const __half* bp = (strm == 0) ? Ahi : (strm == 1) ? Alo : (strm == 2) ? Bhi : Blo;
    const __half* src = bp + (size_t)((strm < 2 ? m0 : n0) + row) * K;
    const uint32_t dst = sbase + (uint32_t)strm * DP_STR + (uint32_t)row * 80u;

    const int sub = lane & 7;
    const int sel = lane >> 3;
    const uint32_t aOff = (uint32_t)(wm * 32 + (sel & 1) * 8 + sub) * 80u + (uint32_t)(sel >> 1) * 16u;
    const uint32_t bOff = (uint32_t)(wn * 32 + (sel & 1) * 8 + sub) * 80u + (uint32_t)(sel >> 1) * 16u;

    float acc[2][4][4];
#pragma unroll
    for (int i = 0; i < 2; i++)
#pragma unroll
        for (int j = 0; j < 4; j++)
#pragma unroll
            for (int q = 0; q < 4; q++) acc[i][j][q] = 0.f;

    const int nk = K >> 5;

#pragma unroll
    for (int p = 0; p < 2; ++p) {
        const uint32_t so = (uint32_t)p * DP_STAGE;
#pragma unroll
        for (int c = 0; c < 4; ++c)
            CPA16(dst + so + (uint32_t)c * 16u, src + p * 32 + c * 8);
        CPA_COMMIT();
    }

    for (int it = 0; it < nk; ++it) {
        CPA_WAIT1();
        __syncthreads();
        if (it + 2 < nk) {
            const uint32_t so = (uint32_t)((it + 2) % 3) * DP_STAGE;
#pragma unroll
            for (int c = 0; c < 4; ++c)
                CPA16(dst + so + (uint32_t)c * 16u, src + (size_t)(it + 2) * 32 + c * 8);
            CPA_COMMIT();
        }
        const uint32_t so = (uint32_t)(it % 3) * DP_STAGE;
#pragma unroll
        for (int q = 0; q < 2; ++q) {
            uint32_t ah4[2][4], al4[2][4];
#pragma unroll
            for (int mf = 0; mf < 2; ++mf) {
                LDSM_X4(ah4[mf], sbase + so + aOff + (uint32_t)mf * 1280u + (uint32_t)q * 32u);
                LDSM_X4(al4[mf], sbase + so + DP_STR + aOff + (uint32_t)mf * 1280u + (uint32_t)q * 32u);
            }
#pragma unroll
            for (int p = 0; p < 2; ++p) {
                uint32_t bh[4], bl[4];
                LDSM_X4(bh, sbase + so + 2 * DP_STR + bOff + (uint32_t)p * 1280u + (uint32_t)q * 32u);
                LDSM_X4(bl, sbase + so + 3 * DP_STR + bOff + (uint32_t)p * 1280u + (uint32_t)q * 32u);
#pragma unroll
                for (int mf = 0; mf < 2; ++mf) {
                    MMA_F16(acc[mf][2 * p],     ah4[mf][0], ah4[mf][1], ah4[mf][2], ah4[mf][3], bh[0], bh[2]);
                    MMA_F16(acc[mf][2 * p + 1], ah4[mf][0], ah4[mf][1], ah4[mf][2], ah4[mf][3], bh[1], bh[3]);
                    MMA_F16(acc[mf][2 * p],     ah4[mf][0], ah4[mf][1], ah4[mf][2], ah4[mf][3], bl[0], bl[2]);
                    MMA_F16(acc[mf][2 * p + 1], ah4[mf][0], ah4[mf][1], ah4[mf][2], ah4[mf][3], bl[1], bl[3]);
                    MMA_F16(acc[mf][2 * p],     al4[mf][0], al4[mf][1], al4[mf][2], al4[mf][3], bh[0], bh[2]);
                    MMA_F16(acc[mf][2 * p + 1], al4[mf][0], al4[mf][1], al4[mf][2], al4[mf][3], bh[1], bh[3]);
                }
            }
        }
    }

    // epilogue: relu(+bias) dot w2, block-reduce per row (same layout/order as R7)
    __syncthreads();
    float (*red)[17] = (float (*)[17])smem;
    const int g = lane >> 2, tg = lane & 3;
    float rs[2][2];
#pragma unroll
    for (int mf = 0; mf < 2; ++mf)
#pragma unroll
        for (int r2 = 0; r2 < 2; ++r2) rs[mf][r2] = 0.f;
#pragma unroll
    for (int nf = 0; nf < 4; ++nf) {
        int col = n0 + wn * 32 + nf * 8 + 2 * tg;
        float2 bb = *(const float2*)(bias + col);
        float2 ww = *(const float2*)(w2 + col);
#pragma unroll
        for (int mf = 0; mf < 2; ++mf)
#pragma unroll
            for (int r2 = 0; r2 < 2; ++r2) {
                rs[mf][r2] += fmaxf(acc[mf][nf][r2 * 2] + bb.x, 0.f) * ww.x
                            + fmaxf(acc[mf][nf][r2 * 2 + 1] + bb.y, 0.f) * ww.y;
            }
    }
#pragma unroll
    for (int mf = 0; mf < 2; ++mf)
#pragma unroll
        for (int r2 = 0; r2 < 2; ++r2)
            red[wm * 32 + mf * 16 + g + r2 * 8][wn * 4 + tg] = rs[mf][r2];
    __syncthreads();
    if (tid < 128) {
        float s = 0.f;
#pragma unroll
        for (int k = 0; k < 16; k++) s += red[tid][k];
        g_entp[blockIdx.y][m0 + tid] = s;
    }
}

// ---------------- tensor-core fp16 GEMM (expert path, 512 thr, k64) ----------
// Block 128x256xk64, 16 warps (4m x 4n), warp tile 32x64, 3 smem stages.
// 144B padded rows (128B data) -> conflict-free LDSM.
#define HROW    144
#define HSM_A   (128 * HROW)               /* 18432 */
#define HSTAGE  (HSM_A + 256 * HROW)       /* 55296 */
#define HSM_TOTAL (1024 + 3 * HSTAGE)      /* 166912 */

template<bool GATHER_A, bool SCATTER_C, bool RELU, bool OUT_HALF>
__global__ __launch_bounds__(512, 1)
void mgemm_h(const __half* __restrict__ A, size_t A_es, int lda,
             const __half* __restrict__ Bt, size_t B_es,
             const float* __restrict__ bias, int bias_es,
             void* __restrict__ Cv, size_t C_es, int ldc, int K)
{
    extern __shared__ __align__(128) char smem[];
    const int e = blockIdx.z;
    const int M = g_cnt[e];
    const int m0 = blockIdx.x * 128;
    if (m0 >= M) return;
    const int n0 = blockIdx.y * 256;

    const uint32_t sbase = smem_to_u32(smem);
    const int tid = threadIdx.x;
    const int lane = tid & 31;
    const int wid = tid >> 5;
    const int wm = wid & 3;       // 4 warps in m (32 rows each)
    const int wn = wid >> 2;      // 4 warps in n (64 cols each)

    const __half* Ae = A + (size_t)e * A_es;
    const __half* Be = Bt + (size_t)e * B_es;
    const float* be = bias + (size_t)e * bias_es;
    const int* le = g_list + (size_t)e * T_TOK;

    int* rowIdx = (int*)smem;
    if (tid < 128) {
        int m = m0 + tid;
        rowIdx[tid] = (m < M) ? le[m] : 0;
    }
    __syncthreads();

    // cp.async: A = 2 chunks/thread, B = 4 chunks/thread (16B chunks, k64 tile)
    const int arow = tid >> 2;                  // 0..127
    const int ach  = tid & 3;                   // 0..3 (chunks ach, ach+4)
    int ar = GATHER_A ? rowIdx[arow] : (m0 + arow);
    const __half* Aptr = Ae + (size_t)ar * lda + ach * 8;
    const uint32_t dA = sbase + 1024 + (uint32_t)arow * HROW + (uint32_t)ach * 16u;

    const int brow = tid >> 1;                  // 0..255
    const int bh2  = tid & 1;                   // half of row: 0 or 1 (64B each)
    const __half* Bptr = Be + (size_t)(n0 + brow) * K + bh2 * 32;
    const uint32_t dB = sbase + 1024 + HSM_A + (uint32_t)brow * HROW + (uint32_t)bh2 * 64u;

    // LDSM bases
    const int sub = lane & 7;
    const int sel = lane >> 3;
    const uint32_t aL = sbase + 1024 +
        (uint32_t)(wm * 32 + (sel & 1) * 8 + sub) * HROW + (uint32_t)(sel >> 1) * 16u;
    const uint32_t bL = sbase + 1024 + HSM_A +
        (uint32_t)(wn * 64 + (sel & 1) * 8 + sub) * HROW + (uint32_t)(sel >> 1) * 16u;

    float acc[2][8][4];
#pragma unroll
    for (int i = 0; i < 2; i++)
#pragma unroll
        for (int j = 0; j < 8; j++)
#pragma unroll
            for (int q = 0; q < 4; q++) acc[i][j][q] = 0.f;

    const int nk = K >> 6;   // k-tiles of 64

    // prologue: tiles 0,1 into stages 0,1
#pragma unroll
    for (int p = 0; p < 2; ++p) {
        const uint32_t so = (uint32_t)p * HSTAGE;
        CPA16(dA + so, Aptr + p * 64);
        CPA16(dA + so + 64, Aptr + p * 64 + 32);
#pragma unroll
        for (int c = 0; c < 4; ++c)
            CPA16(dB + so + (uint32_t)c * 16u, Bptr + p * 64 + c * 8);
        CPA_COMMIT();
    }

    for (int it = 0; it < nk; ++it) {
        CPA_WAIT1();
        __syncthreads();
        if (it + 2 < nk) {
            const uint32_t so = (uint32_t)((it + 2) % 3) * HSTAGE;
            CPA16(dA + so, Aptr + (size_t)(it + 2) * 64);
            CPA16(dA + so + 64, Aptr + (size_t)(it + 2) * 64 + 32);
#pragma unroll
            for (int c = 0; c < 4; ++c)
                CPA16(dB + so + (uint32_t)c * 16u, Bptr + (size_t)(it + 2) * 64 + c * 8);
            CPA_COMMIT();
        }
        const uint32_t so = (uint32_t)(it % 3) * HSTAGE;
#pragma unroll
        for (int q = 0; q < 4; ++q) {            // four k16 steps
            uint32_t af[2][4];
#pragma unroll
            for (int mf = 0; mf < 2; ++mf)
                LDSM_X4(af[mf], aL + so + (uint32_t)mf * (16u * HROW) + (uint32_t)q * 32u);
#pragma unroll
            for (int p = 0; p < 4; ++p) {
                uint32_t bf[4];
                LDSM_X4(bf, bL + so + (uint32_t)p * (16u * HROW) + (uint32_t)q * 32u);
#pragma unroll
                for (int mf = 0; mf < 2; ++mf) {
                    MMA_F16(acc[mf][2 * p],     af[mf][0], af[mf][1], af[mf][2], af[mf][3], bf[0], bf[2]);
                    MMA_F16(acc[mf][2 * p + 1], af[mf][0], af[mf][1], af[mf][2], af[mf][3], bf[1], bf[3]);
                }
            }
        }
    }

    // epilogue
    const int g = lane >> 2, tg = lane & 3;
#pragma unroll
    for (int mf = 0; mf < 2; ++mf) {
#pragma unroll
        for (int r2 = 0; r2 < 2; ++r2) {
            int mloc = wm * 32 + mf * 16 + g + r2 * 8;
            if (m0 + mloc >= M) continue;
            int orow = SCATTER_C ? rowIdx[mloc] : (m0 + mloc);
#pragma unroll
            for (int nf = 0; nf < 8; ++nf) {
                int col = wn * 64 + nf * 8 + 2 * tg;
                float2 bb = *(const float2*)(be + n0 + col);
                float vx = acc[mf][nf][r2 * 2] + bb.x;
                float vy = acc[mf][nf][r2 * 2 + 1] + bb.y;
                if (RELU) { vx = fmaxf(vx, 0.f); vy = fmaxf(vy, 0.f); }
                if (OUT_HALF) {
                    __half* dst = (__half*)Cv + (size_t)e * C_es + (size_t)orow * ldc + n0 + col;
                    *(__half2*)dst = __floats2half2_rn(vx, vy);
                } else {
                    float* dst = (float*)Cv + (size_t)e * C_es + (size_t)orow * ldc + n0 + col;
                    float2 v; v.x = vx; v.y = vy;
                    *(float2*)dst = v;
                }
            }
        }
    }
}

// ---------------- routing ----------------------------------------------------
__global__ void route_kernel(const float* __restrict__ x,
                             const float* __restrict__ dp_b2,
                             const float* __restrict__ gate_w,
                             const float* __restrict__ gate_b)
{
    int warp = (blockIdx.x * blockDim.x + threadIdx.x) >> 5;
    int lane = threadIdx.x & 31;
    if (warp >= T_TOK) return;

    const float* xr = x + (size_t)warp * D_DIM;
    float l0 = 0.f, l1 = 0.f, l2 = 0.f, l3 = 0.f;
    for (int j = lane; j < D_DIM; j += 32) {
        float xv = xr[j];
        float4 gw = *(const float4*)(gate_w + (size_t)j * 4);
        l0 += xv * gw.x; l1 += xv * gw.y; l2 += xv * gw.z; l3 += xv * gw.w;
    }
#pragma unroll
    for (int off = 16; off; off >>= 1) {
        l0 += __shfl_down_sync(0xffffffffu, l0, off);
        l1 += __shfl_down_sync(0xffffffffu, l1, off);
        l2 += __shfl_down_sync(0xffffffffu, l2, off);
        l3 += __shfl_down_sync(0xffffffffu, l3, off);
    }
    if (lane != 0) return;

    float ent = ((g_entp[0][warp] + g_entp[1][warp]) +
                 (g_entp[2][warp] + g_entp[3][warp])) + dp_b2[0];
    ent = fmaxf(ent, 0.f) + log1pf(expf(-fabsf(ent)));
    float norm = fminf(fmaxf((ent - 0.5f) / 1.5f, 0.f), 1.f);
    int k = (int)rintf(1.0f + norm * 3.0f);
    k = max(1, min(E_EXP, k));

    float lg[4] = { l0 + gate_b[0], l1 + gate_b[1], l2 + gate_b[2], l3 + gate_b[3] };
    int idx[4] = { 0, 1, 2, 3 };
#pragma unroll
    for (int a = 0; a < 3; a++) {
        int best = a;
#pragma unroll
        for (int b = a + 1; b < 4; b++)
            if (lg[idx[b]] > lg[idx[best]]) best = b;
        int t = idx[a]; idx[a] = idx[best]; idx[best] = t;
    }
    float mx = lg[idx[0]];
    float w[4]; float wsum = 0.f;
#pragma unroll
    for (int j = 0; j < 4; j++) {
        w[j] = (j < k) ? expf(lg[idx[j]] - mx) : 0.f;
        wsum += w[j];
    }
    float inv = 1.f / wsum;
    float dw[4] = { 0.f, 0.f, 0.f, 0.f };
#pragma unroll
    for (int j = 0; j < 4; j++)
        if (j < k) dw[idx[j]] = w[j] * inv;
#pragma unroll
    for (int e2 = 0; e2 < 4; e2++) g_dw[(size_t)warp * 4 + e2] = dw[e2];

    for (int j = 0; j < k; j++) {
        int ex = idx[j];
        int p = atomicAdd(&g_cnt[ex], 1);
        g_list[(size_t)ex * T_TOK + p] = warp;
    }
}

// ---------------- combine ----------------------------------------------------
__global__ void combine_kernel(float* __restrict__ out)
{
    const size_t P = (size_t)T_TOK * D_DIM / 4;
    size_t i = (size_t)blockIdx.x * blockDim.x + threadIdx.x;
    if (i >= P) return;
    int t = (int)(i >> 8);
    float w0 = g_dw[(size_t)t * 4 + 0];
    float w1 = g_dw[(size_t)t * 4 + 1];
    float w2 = g_dw[(size_t)t * 4 + 2];
    float w3 = g_dw[(size_t)t * 4 + 3];
    const float4* y4 = (const float4*)g_y;
    float4 o = make_float4(0.f, 0.f, 0.f, 0.f);
    if (w0 != 0.f) { float4 a = y4[i];
        o.x += w0 * a.x; o.y += w0 * a.y; o.z += w0 * a.z; o.w += w0 * a.w; }
    if (w1 != 0.f) { float4 a = y4[P + i];
        o.x += w1 * a.x; o.y += w1 * a.y; o.z += w1 * a.z; o.w += w1 * a.w; }
    if (w2 != 0.f) { float4 a = y4[2 * P + i];
        o.x += w2 * a.x; o.y += w2 * a.y; o.z += w2 * a.z; o.w += w2 * a.w; }
    if (w3 != 0.f) { float4 a = y4[3 * P + i];
        o.x += w3 * a.x; o.y += w3 * a.y; o.z += w3 * a.z; o.w += w3 * a.w; }
    ((float4*)out)[i] = o;
}

// ---------------- launch -----------------------------------------------------
extern "C" void kernel_launch(void* const* d_in, const int* in_sizes, int n_in,
                              void* d_out, int out_size)
{
    (void)in_sizes; (void)n_in; (void)out_size;
    const float* x      = (const float*)d_in[0];
    const float* gate_w = (const float*)d_in[1];
    const float* gate_b = (const float*)d_in[2];
    const float* dp_w1  = (const float*)d_in[3];
    const float* dp_b1  = (const float*)d_in[4];
    const float* dp_w2  = (const float*)d_in[5];
    const float* dp_b2  = (const float*)d_in[6];
    const float* ew1    = (const float*)d_in[7];
    const float* eb1    = (const float*)d_in[8];
    const float* ew2    = (const float*)d_in[9];
    const float* eb2    = (const float*)d_in[10];
    float* out = (float*)d_out;

    void *p_xh, *p_xlo, *p_hidh, *p_y, *p_w1t, *p_w2t, *p_dwhi, *p_dwlo;
    cudaGetSymbolAddress(&p_xh,   g_xh);
    cudaGetSymbolAddress(&p_xlo,  g_xlo);
    cudaGetSymbolAddress(&p_hidh, g_hidh);
    cudaGetSymbolAddress(&p_y,    g_y);
    cudaGetSymbolAddress(&p_w1t,  g_w1t);
    cudaGetSymbolAddress(&p_w2t,  g_w2t);
    cudaGetSymbolAddress(&p_dwhi, g_dwhi);
    cudaGetSymbolAddress(&p_dwlo, g_dwlo);
    __half* sxh  = (__half*)p_xh;
    __half* sxlo = (__half*)p_xlo;
    __half* shid = (__half*)p_hidh;
    float*  sy   = (float*)p_y;
    __half* w1t  = (__half*)p_w1t;
    __half* w2t  = (__half*)p_w2t;
    __half* dwhi = (__half*)p_dwhi;
    __half* dwlo = (__half*)p_dwlo;

    cudaFuncSetAttribute(mgemm_h<true, false, true, true>,
                         cudaFuncAttributeMaxDynamicSharedMemorySize, HSM_TOTAL);
    cudaFuncSetAttribute(mgemm_h<false, true, false, false>,
                         cudaFuncAttributeMaxDynamicSharedMemorySize, HSM_TOTAL);
    cudaFuncSetAttribute(dptc_k,
                         cudaFuncAttributeMaxDynamicSharedMemorySize, DP_TOTAL);

    // 1. zero expert counters
    init_kernel<<<1, 32>>>();

    // 2. x -> fp16 hi/lo; weight transposes
    xsplit_k<<<(T_TOK * D_DIM / 4) / 256, 256>>>(x, sxh, sxlo);
    transpose_hl_k<<<dim3(DP_H / 32, D_DIM / 32, 1), dim3(32, 8)>>>(dp_w1, dwhi, dwlo, D_DIM, DP_H);
    transpose_k<<<dim3(H_DIM / 32, D_DIM / 32, E_EXP), dim3(32, 8)>>>(ew1, w1t, D_DIM, H_DIM);
    transpose_k<<<dim3(D_DIM / 32, H_DIM / 32, E_EXP), dim3(32, 8)>>>(ew2, w2t, H_DIM, D_DIM);

    // 3. dp GEMM on tensor cores (fp16x3 split, 512 thr) + fused entropy
    dptc_k<<<dim3(T_TOK / 128, DP_H / 128), 512, DP_TOTAL>>>(
        sxh, sxlo, dwhi, dwlo, dp_b1, dp_w2);

    // 4. routing (exact fp32 logits + deterministic entropy partial sum)
    route_kernel<<<(T_TOK * 32) / 256, 256>>>(x, dp_b2, gate_w, gate_b);

    // 5. expert GEMM1 (fp16 mma, gathered A): hid = relu(Xh[list] @ W1 + b1) -> fp16
    mgemm_h<true, false, true, true><<<dim3(T_TOK / 128, H_DIM / 256, E_EXP), 512, HSM_TOTAL>>>(
        sxh, 0, D_DIM, w1t, (size_t)D_DIM * H_DIM, eb1, H_DIM,
        shid, (size_t)T_TOK * H_DIM, H_DIM, D_DIM);

    // 6. expert GEMM2 (fp16 mma, scattered C): y[tok] = hid @ W2 + b2 -> fp32
    mgemm_h<false, true, false, false><<<dim3(T_TOK / 128, D_DIM / 256, E_EXP), 512, HSM_TOTAL>>>(
        shid, (size_t)T_TOK * H_DIM, H_DIM, w2t, (size_t)H_DIM * D_DIM, eb2, D_DIM,
        sy, (size_t)T_TOK * D_DIM, D_DIM, H_DIM);

    // 7. weighted combine
    combine_kernel<<<(T_TOK * D_DIM / 4) / 256, 256>>>(out);
}

// round 13
// speedup vs baseline: 1.0826x; 1.0826x over previous
#include <cuda_runtime.h>
#include <cuda.h>
#include <cuda_fp16.h>
#include <math.h>
#include <stdint.h>

#define T_TOK 8192
#define D_DIM 1024
#define H_DIM 2048
#define E_EXP 4
#define DP_H  512

// ---------------- scratch (device globals; no allocations) -------------------
__device__ __half g_xh  [(size_t)T_TOK * D_DIM];           // x hi (fp16)
__device__ __half g_xlo [(size_t)T_TOK * D_DIM];           // x lo (fp16)
__device__ __half g_hidh[(size_t)E_EXP * T_TOK * H_DIM];   // expert hidden fp16
__device__ float  g_y   [(size_t)E_EXP * T_TOK * D_DIM];   // expert outputs
__device__ __half g_w1t [(size_t)E_EXP * D_DIM * H_DIM];   // [E][H][D] K-contig fp16
__device__ __half g_w2t [(size_t)E_EXP * H_DIM * D_DIM];   // [E][D][H] K-contig fp16
__device__ __half g_dwhi[(size_t)DP_H * D_DIM];            // dp_w1^T hi [512][1024]
__device__ __half g_dwlo[(size_t)DP_H * D_DIM];            // dp_w1^T lo
__device__ float  g_entp[4][T_TOK];                        // dp entropy partials
__device__ float  g_dw  [(size_t)T_TOK * E_EXP];
__device__ int    g_cnt [E_EXP];
__device__ int    g_list[(size_t)E_EXP * T_TOK];

// ---------------- helpers ----------------------------------------------------
__device__ __forceinline__ uint32_t smem_to_u32(const void* p) {
    uint32_t a;
    asm("{ .reg .u64 t; cvta.to.shared.u64 t, %1; cvt.u32.u64 %0, t; }" : "=r"(a) : "l"(p));
    return a;
}

#define CPA16(dst, src) \
    asm volatile("cp.async.cg.shared.global [%0], [%1], 16;" :: "r"(dst), "l"(src) : "memory")
#define CPA_COMMIT() asm volatile("cp.async.commit_group;" ::: "memory")
#define CPA_WAIT1()  asm volatile("cp.async.wait_group 1;" ::: "memory")
#define CPA_WAIT2()  asm volatile("cp.async.wait_group 2;" ::: "memory")

#define LDSM_X4(r, addr) \
    asm volatile("ldmatrix.sync.aligned.m8n8.x4.shared.b16 {%0,%1,%2,%3}, [%4];" \
        : "=r"((r)[0]), "=r"((r)[1]), "=r"((r)[2]), "=r"((r)[3]) : "r"(addr))

#define MMA_F16(c, a0, a1, a2, a3, b0, b1) \
    asm volatile("mma.sync.aligned.m16n8k16.row.col.f32.f16.f16.f32 " \
        "{%0,%1,%2,%3}, {%4,%5,%6,%7}, {%8,%9}, {%0,%1,%2,%3};" \
        : "+f"((c)[0]), "+f"((c)[1]), "+f"((c)[2]), "+f"((c)[3]) \
        : "r"(a0), "r"(a1), "r"(a2), "r"(a3), "r"(b0), "r"(b1))

// ---------------- init -------------------------------------------------------
__global__ void init_kernel() {
    if (threadIdx.x < E_EXP) g_cnt[threadIdx.x] = 0;
}

// ---------------- x -> fp16 hi + lo ------------------------------------------
__global__ void xsplit_k(const float* __restrict__ in,
                         __half* __restrict__ hi, __half* __restrict__ lo) {
    size_t i = (size_t)blockIdx.x * blockDim.x + threadIdx.x;
    float4 v = ((const float4*)in)[i];
    __half2 h0 = __floats2half2_rn(v.x, v.y);
    __half2 h1 = __floats2half2_rn(v.z, v.w);
    __half2 l0 = __floats2half2_rn(v.x - __low2float(h0), v.y - __high2float(h0));
    __half2 l1 = __floats2half2_rn(v.z - __low2float(h1), v.w - __high2float(h1));
    __half2 hh[2] = { h0, h1 };
    __half2 ll[2] = { l0, l1 };
    ((uint2*)hi)[i] = *(uint2*)hh;
    ((uint2*)lo)[i] = *(uint2*)ll;
}

// ---------------- transpose: in [z][R][C] f32 -> out [z][C][R] fp16 ----------
__global__ void transpose_k(const float* __restrict__ in, __half* __restrict__ out,
                            int R, int C) {
    __shared__ float t[32][33];
    int z = blockIdx.z;
    const float* I = in + (size_t)z * R * C;
    __half* O = out + (size_t)z * R * C;
    int r0 = blockIdx.y * 32, c0 = blockIdx.x * 32;
    int tx = threadIdx.x, ty = threadIdx.y;  // 32 x 8
#pragma unroll
    for (int i = 0; i < 32; i += 8)
        t[ty + i][tx] = I[(size_t)(r0 + ty + i) * C + c0 + tx];
    __syncthreads();
#pragma unroll
    for (int i = 0; i < 32; i += 8)
        O[(size_t)(c0 + ty + i) * R + r0 + tx] = __float2half_rn(t[tx][ty + i]);
}

// ---------------- transpose with hi/lo split: [R][C] f32 -> [C][R] fp16 x2 ---
__global__ void transpose_hl_k(const float* __restrict__ in,
                               __half* __restrict__ ohi, __half* __restrict__ olo,
                               int R, int C) {
    __shared__ float t[32][33];
    int r0 = blockIdx.y * 32, c0 = blockIdx.x * 32;
    int tx = threadIdx.x, ty = threadIdx.y;  // 32 x 8
#pragma unroll
    for (int i = 0; i < 32; i += 8)
        t[ty + i][tx] = in[(size_t)(r0 + ty + i) * C + c0 + tx];
    __syncthreads();
#pragma unroll
    for (int i = 0; i < 32; i += 8) {
        float v = t[tx][ty + i];
        __half h = __float2half_rn(v);
        __half l = __float2half_rn(v - __half2float(h));
        ohi[(size_t)(c0 + ty + i) * R + r0 + tx] = h;
        olo[(size_t)(c0 + ty + i) * R + r0 + tx] = l;
    }
}

// ---------------- tensor-core fp16x3 dp GEMM + fused entropy (512 thr) -------
// h = relu(X @ W1^T + b1), 3-term split; g_entp[by][t] = sum h*w2 over 128-col
// slab. Block 128x128xk32, 16 warps (4m x 4n), warp tile 32x32, 3 stages.
#define DP_STR  10240              /* one 128x(32h) stream, 80B rows */
#define DP_STAGE (4 * DP_STR)
#define DP_TOTAL (1024 + 3 * DP_STAGE)

__global__ __launch_bounds__(512, 1)
void dptc_k(const __half* __restrict__ Ahi, const __half* __restrict__ Alo,
            const __half* __restrict__ Bhi, const __half* __restrict__ Blo,
            const float* __restrict__ bias, const float* __restrict__ w2)
{
    extern __shared__ __align__(128) char smem[];
    const int m0 = blockIdx.x * 128;
    const int n0 = blockIdx.y * 128;
    const uint32_t sbase = smem_to_u32(smem) + 1024;
    const int tid = threadIdx.x;
    const int lane = tid & 31;
    const int wid = tid >> 5;
    const int wm = wid & 3;       // 4 warps in m (32 rows)
    const int wn = wid >> 2;      // 4 warps in n (32 cols)
    const int K = D_DIM;

    // cp.async: thread covers stream (tid>>7), row (tid&127), 4x16B chunks
    const int strm = tid >> 7;
    const int row = tid & 127;
    const __half* bp = (strm == 0) ? Ahi : (strm == 1) ? Alo : (strm == 2) ? Bhi : Blo;
    const __half* src = bp + (size_t)((strm < 2 ? m0 : n0) + row) * K;
    const uint32_t dst = sbase + (uint32_t)strm * DP_STR + (uint32_t)row * 80u;

    const int sub = lane & 7;
    const int sel = lane >> 3;
    const uint32_t aOff = (uint32_t)(wm * 32 + (sel & 1) * 8 + sub) * 80u + (uint32_t)(sel >> 1) * 16u;
    const uint32_t bOff = (uint32_t)(wn * 32 + (sel & 1) * 8 + sub) * 80u + (uint32_t)(sel >> 1) * 16u;

    float acc[2][4][4];
#pragma unroll
    for (int i = 0; i < 2; i++)
#pragma unroll
        for (int j = 0; j < 4; j++)
#pragma unroll
            for (int q = 0; q < 4; q++) acc[i][j][q] = 0.f;

    const int nk = K >> 5;

#pragma unroll
    for (int p = 0; p < 2; ++p) {
        const uint32_t so = (uint32_t)p * DP_STAGE;
#pragma unroll
        for (int c = 0; c < 4; ++c)
            CPA16(dst + so + (uint32_t)c * 16u, src + p * 32 + c * 8);
        CPA_COMMIT();
    }

    for (int it = 0; it < nk; ++it) {
        CPA_WAIT1();
        __syncthreads();
        if (it + 2 < nk) {
            const uint32_t so = (uint32_t)((it + 2) % 3) * DP_STAGE;
#pragma unroll
            for (int c = 0; c < 4; ++c)
                CPA16(dst + so + (uint32_t)c * 16u, src + (size_t)(it + 2) * 32 + c * 8);
            CPA_COMMIT();
        }
        const uint32_t so = (uint32_t)(it % 3) * DP_STAGE;
#pragma unroll
        for (int q = 0; q < 2; ++q) {
            uint32_t ah4[2][4], al4[2][4];
#pragma unroll
            for (int mf = 0; mf < 2; ++mf) {
                LDSM_X4(ah4[mf], sbase + so + aOff + (uint32_t)mf * 1280u + (uint32_t)q * 32u);
                LDSM_X4(al4[mf], sbase + so + DP_STR + aOff + (uint32_t)mf * 1280u + (uint32_t)q * 32u);
            }
#pragma unroll
            for (int p = 0; p < 2; ++p) {
                uint32_t bh[4], bl[4];
                LDSM_X4(bh, sbase + so + 2 * DP_STR + bOff + (uint32_t)p * 1280u + (uint32_t)q * 32u);
                LDSM_X4(bl, sbase + so + 3 * DP_STR + bOff + (uint32_t)p * 1280u + (uint32_t)q * 32u);
#pragma unroll
                for (int mf = 0; mf < 2; ++mf) {
                    MMA_F16(acc[mf][2 * p],     ah4[mf][0], ah4[mf][1], ah4[mf][2], ah4[mf][3], bh[0], bh[2]);
                    MMA_F16(acc[mf][2 * p + 1], ah4[mf][0], ah4[mf][1], ah4[mf][2], ah4[mf][3], bh[1], bh[3]);
                    MMA_F16(acc[mf][2 * p],     ah4[mf][0], ah4[mf][1], ah4[mf][2], ah4[mf][3], bl[0], bl[2]);
                    MMA_F16(acc[mf][2 * p + 1], ah4[mf][0], ah4[mf][1], ah4[mf][2], ah4[mf][3], bl[1], bl[3]);
                    MMA_F16(acc[mf][2 * p],     al4[mf][0], al4[mf][1], al4[mf][2], al4[mf][3], bh[0], bh[2]);
                    MMA_F16(acc[mf][2 * p + 1], al4[mf][0], al4[mf][1], al4[mf][2], al4[mf][3], bh[1], bh[3]);
                }
            }
        }
    }

    // epilogue: relu(+bias) dot w2, block-reduce per row (same layout/order as R7)
    __syncthreads();
    float (*red)[17] = (float (*)[17])smem;
    const int g = lane >> 2, tg = lane & 3;
    float rs[2][2];
#pragma unroll
    for (int mf = 0; mf < 2; ++mf)
#pragma unroll
        for (int r2 = 0; r2 < 2; ++r2) rs[mf][r2] = 0.f;
#pragma unroll
    for (int nf = 0; nf < 4; ++nf) {
        int col = n0 + wn * 32 + nf * 8 + 2 * tg;
        float2 bb = *(const float2*)(bias + col);
        float2 ww = *(const float2*)(w2 + col);
#pragma unroll
        for (int mf = 0; mf < 2; ++mf)
#pragma unroll
            for (int r2 = 0; r2 < 2; ++r2) {
                rs[mf][r2] += fmaxf(acc[mf][nf][r2 * 2] + bb.x, 0.f) * ww.x
                            + fmaxf(acc[mf][nf][r2 * 2 + 1] + bb.y, 0.f) * ww.y;
            }
    }
#pragma unroll
    for (int mf = 0; mf < 2; ++mf)
#pragma unroll
        for (int r2 = 0; r2 < 2; ++r2)
            red[wm * 32 + mf * 16 + g + r2 * 8][wn * 4 + tg] = rs[mf][r2];
    __syncthreads();
    if (tid < 128) {
        float s = 0.f;
#pragma unroll
        for (int k = 0; k < 16; k++) s += red[tid][k];
        g_entp[blockIdx.y][m0 + tid] = s;
    }
}

// ---------------- tensor-core fp16 GEMM (expert path, R7 proven config) ------
// Block 128x256xk32, 16 warps (4m x 4n), warp tile 32x64, 4 smem stages.
#define HSM_A   10240              /* 128*80 */
#define HSTAGE  30720              /* A + 256*80 */
#define HSM_TOTAL (1024 + 4 * HSTAGE)

template<bool GATHER_A, bool SCATTER_C, bool RELU, bool OUT_HALF>
__global__ __launch_bounds__(512, 1)
void mgemm_h(const __half* __restrict__ A, size_t A_es, int lda,
             const __half* __restrict__ Bt, size_t B_es,
             const float* __restrict__ bias, int bias_es,
             void* __restrict__ Cv, size_t C_es, int ldc, int K)
{
    extern __shared__ __align__(128) char smem[];
    const int e = blockIdx.z;
    const int M = g_cnt[e];
    const int m0 = blockIdx.x * 128;
    if (m0 >= M) return;
    const int n0 = blockIdx.y * 256;

    const uint32_t sbase = smem_to_u32(smem);
    const int tid = threadIdx.x;
    const int lane = tid & 31;
    const int wid = tid >> 5;
    const int wm = wid & 3;       // 4 warps in m (32 rows each)
    const int wn = wid >> 2;      // 4 warps in n (64 cols each)

    const __half* Ae = A + (size_t)e * A_es;
    const __half* Be = Bt + (size_t)e * B_es;
    const float* be = bias + (size_t)e * bias_es;
    const int* le = g_list + (size_t)e * T_TOK;

    int* rowIdx = (int*)smem;
    if (tid < 128) {
        int m = m0 + tid;
        rowIdx[tid] = (m < M) ? le[m] : 0;
    }
    __syncthreads();

    // cp.async mapping: A = 1 chunk/thread, B = 2 chunks/thread (16B chunks)
    const int arow = tid >> 2;                  // 0..127
    const int ach  = tid & 3;                   // 0..3
    int ar = GATHER_A ? rowIdx[arow] : (m0 + arow);
    const __half* Aptr = Ae + (size_t)ar * lda + ach * 8;
    const uint32_t dA = sbase + 1024 + (uint32_t)arow * 80u + (uint32_t)ach * 16u;

    const int br0 = tid >> 2;                   // B rows 0..127
    const int br1 = br0 + 128;                  // B rows 128..255
    const int bs  = tid & 3;
    const __half* Bp0 = Be + (size_t)(n0 + br0) * K + bs * 8;
    const __half* Bp1 = Be + (size_t)(n0 + br1) * K + bs * 8;
    const uint32_t dB0 = sbase + 1024 + HSM_A + (uint32_t)br0 * 80u + (uint32_t)bs * 16u;
    const uint32_t dB1 = sbase + 1024 + HSM_A + (uint32_t)br1 * 80u + (uint32_t)bs * 16u;

    // LDSM bases
    const int sub = lane & 7;
    const int sel = lane >> 3;
    const uint32_t aL = sbase + 1024 +
        (uint32_t)(wm * 32 + (sel & 1) * 8 + sub) * 80u + (uint32_t)(sel >> 1) * 16u;
    const uint32_t bL = sbase + 1024 + HSM_A +
        (uint32_t)(wn * 64 + (sel & 1) * 8 + sub) * 80u + (uint32_t)(sel >> 1) * 16u;

    float acc[2][8][4];
#pragma unroll
    for (int i = 0; i < 2; i++)
#pragma unroll
        for (int j = 0; j < 8; j++)
#pragma unroll
            for (int q = 0; q < 4; q++) acc[i][j][q] = 0.f;

    const int nk = K >> 5;

    // prologue: tiles 0..2 into stages 0..2
#pragma unroll
    for (int p = 0; p < 3; ++p) {
        const uint32_t so = (uint32_t)p * HSTAGE;
        CPA16(dA + so, Aptr + p * 32);
        CPA16(dB0 + so, Bp0 + p * 32);
        CPA16(dB1 + so, Bp1 + p * 32);
        CPA_COMMIT();
    }

    for (int it = 0; it < nk; ++it) {
        CPA_WAIT2();
        __syncthreads();
        if (it + 3 < nk) {
            const uint32_t so = (uint32_t)((it + 3) & 3) * HSTAGE;
            CPA16(dA + so, Aptr + (size_t)(it + 3) * 32);
            CPA16(dB0 + so, Bp0 + (size_t)(it + 3) * 32);
            CPA16(dB1 + so, Bp1 + (size_t)(it + 3) * 32);
            CPA_COMMIT();
        }
        const uint32_t so = (uint32_t)(it & 3) * HSTAGE;
#pragma unroll
        for (int q = 0; q < 2; ++q) {
            uint32_t af[2][4];
#pragma unroll
            for (int mf = 0; mf < 2; ++mf)
                LDSM_X4(af[mf], aL + so + (uint32_t)mf * 1280u + (uint32_t)q * 32u);
#pragma unroll
            for (int p = 0; p < 4; ++p) {
                uint32_t bf[4];
                LDSM_X4(bf, bL + so + (uint32_t)p * 1280u + (uint32_t)q * 32u);
#pragma unroll
                for (int mf = 0; mf < 2; ++mf) {
                    MMA_F16(acc[mf][2 * p],     af[mf][0], af[mf][1], af[mf][2], af[mf][3], bf[0], bf[2]);
                    MMA_F16(acc[mf][2 * p + 1], af[mf][0], af[mf][1], af[mf][2], af[mf][3], bf[1], bf[3]);
                }
            }
        }
    }

    // epilogue
    const int g = lane >> 2, tg = lane & 3;
#pragma unroll
    for (int mf = 0; mf < 2; ++mf) {
#pragma unroll
        for (int r2 = 0; r2 < 2; ++r2) {
            int mloc = wm * 32 + mf * 16 + g + r2 * 8;
            if (m0 + mloc >= M) continue;
            int orow = SCATTER_C ? rowIdx[mloc] : (m0 + mloc);
#pragma unroll
            for (int nf = 0; nf < 8; ++nf) {
                int col = wn * 64 + nf * 8 + 2 * tg;
                float2 bb = *(const float2*)(be + n0 + col);
                float vx = acc[mf][nf][r2 * 2] + bb.x;
                float vy = acc[mf][nf][r2 * 2 + 1] + bb.y;
                if (RELU) { vx = fmaxf(vx, 0.f); vy = fmaxf(vy, 0.f); }
                if (OUT_HALF) {
                    __half* dst = (__half*)Cv + (size_t)e * C_es + (size_t)orow * ldc + n0 + col;
                    *(__half2*)dst = __floats2half2_rn(vx, vy);
                } else {
                    float* dst = (float*)Cv + (size_t)e * C_es + (size_t)orow * ldc + n0 + col;
                    float2 v; v.x = vx; v.y = vy;
                    *(float2*)dst = v;
                }
            }
        }
    }
}

// ---------------- routing ----------------------------------------------------
__global__ void route_kernel(const float* __restrict__ x,
                             const float* __restrict__ dp_b2,
                             const float* __restrict__ gate_w,
                             const float* __restrict__ gate_b)
{
    int warp = (blockIdx.x * blockDim.x + threadIdx.x) >> 5;
    int lane = threadIdx.x & 31;
    if (warp >= T_TOK) return;

    const float* xr = x + (size_t)warp * D_DIM;
    float l0 = 0.f, l1 = 0.f, l2 = 0.f, l3 = 0.f;
    for (int j = lane; j < D_DIM; j += 32) {
        float xv = xr[j];
        float4 gw = *(const float4*)(gate_w + (size_t)j * 4);
        l0 += xv * gw.x; l1 += xv * gw.y; l2 += xv * gw.z; l3 += xv * gw.w;
    }
#pragma unroll
    for (int off = 16; off; off >>= 1) {
        l0 += __shfl_down_sync(0xffffffffu, l0, off);
        l1 += __shfl_down_sync(0xffffffffu, l1, off);
        l2 += __shfl_down_sync(0xffffffffu, l2, off);
        l3 += __shfl_down_sync(0xffffffffu, l3, off);
    }
    if (lane != 0) return;

    float ent = ((g_entp[0][warp] + g_entp[1][warp]) +
                 (g_entp[2][warp] + g_entp[3][warp])) + dp_b2[0];
    ent = fmaxf(ent, 0.f) + log1pf(expf(-fabsf(ent)));
    float norm = fminf(fmaxf((ent - 0.5f) / 1.5f, 0.f), 1.f);
    int k = (int)rintf(1.0f + norm * 3.0f);
    k = max(1, min(E_EXP, k));

    float lg[4] = { l0 + gate_b[0], l1 + gate_b[1], l2 + gate_b[2], l3 + gate_b[3] };
    int idx[4] = { 0, 1, 2, 3 };
#pragma unroll
    for (int a = 0; a < 3; a++) {
        int best = a;
#pragma unroll
        for (int b = a + 1; b < 4; b++)
            if (lg[idx[b]] > lg[idx[best]]) best = b;
        int t = idx[a]; idx[a] = idx[best]; idx[best] = t;
    }
    float mx = lg[idx[0]];
    float w[4]; float wsum = 0.f;
#pragma unroll
    for (int j = 0; j < 4; j++) {
        w[j] = (j < k) ? expf(lg[idx[j]] - mx) : 0.f;
        wsum += w[j];
    }
    float inv = 1.f / wsum;
    float dw[4] = { 0.f, 0.f, 0.f, 0.f };
#pragma unroll
    for (int j = 0; j < 4; j++)
        if (j < k) dw[idx[j]] = w[j] * inv;
#pragma unroll
    for (int e2 = 0; e2 < 4; e2++) g_dw[(size_t)warp * 4 + e2] = dw[e2];

    for (int j = 0; j < k; j++) {
        int ex = idx[j];
        int p = atomicAdd(&g_cnt[ex], 1);
        g_list[(size_t)ex * T_TOK + p] = warp;
    }
}

// ---------------- combine ----------------------------------------------------
__global__ void combine_kernel(float* __restrict__ out)
{
    const size_t P = (size_t)T_TOK * D_DIM / 4;
    size_t i = (size_t)blockIdx.x * blockDim.x + threadIdx.x;
    if (i >= P) return;
    int t = (int)(i >> 8);
    float w0 = g_dw[(size_t)t * 4 + 0];
    float w1 = g_dw[(size_t)t * 4 + 1];
    float w2 = g_dw[(size_t)t * 4 + 2];
    float w3 = g_dw[(size_t)t * 4 + 3];
    const float4* y4 = (const float4*)g_y;
    float4 o = make_float4(0.f, 0.f, 0.f, 0.f);
    if (w0 != 0.f) { float4 a = y4[i];
        o.x += w0 * a.x; o.y += w0 * a.y; o.z += w0 * a.z; o.w += w0 * a.w; }
    if (w1 != 0.f) { float4 a = y4[P + i];
        o.x += w1 * a.x; o.y += w1 * a.y; o.z += w1 * a.z; o.w += w1 * a.w; }
    if (w2 != 0.f) { float4 a = y4[2 * P + i];
        o.x += w2 * a.x; o.y += w2 * a.y; o.z += w2 * a.z; o.w += w2 * a.w; }
    if (w3 != 0.f) { float4 a = y4[3 * P + i];
        o.x += w3 * a.x; o.y += w3 * a.y; o.z += w3 * a.z; o.w += w3 * a.w; }
    ((float4*)out)[i] = o;
}

// ---------------- launch -----------------------------------------------------
extern "C" void kernel_launch(void* const* d_in, const int* in_sizes, int n_in,
                              void* d_out, int out_size)
{
    (void)in_sizes; (void)n_in; (void)out_size;
    const float* x      = (const float*)d_in[0];
    const float* gate_w = (const float*)d_in[1];
    const float* gate_b = (const float*)d_in[2];
    const float* dp_w1  = (const float*)d_in[3];
    const float* dp_b1  = (const float*)d_in[4];
    const float* dp_w2  = (const float*)d_in[5];
    const float* dp_b2  = (const float*)d_in[6];
    const float* ew1    = (const float*)d_in[7];
    const float* eb1    = (const float*)d_in[8];
    const float* ew2    = (const float*)d_in[9];
    const float* eb2    = (const float*)d_in[10];
    float* out = (float*)d_out;

    void *p_xh, *p_xlo, *p_hidh, *p_y, *p_w1t, *p_w2t, *p_dwhi, *p_dwlo;
    cudaGetSymbolAddress(&p_xh,   g_xh);
    cudaGetSymbolAddress(&p_xlo,  g_xlo);
    cudaGetSymbolAddress(&p_hidh, g_hidh);
    cudaGetSymbolAddress(&p_y,    g_y);
    cudaGetSymbolAddress(&p_w1t,  g_w1t);
    cudaGetSymbolAddress(&p_w2t,  g_w2t);
    cudaGetSymbolAddress(&p_dwhi, g_dwhi);
    cudaGetSymbolAddress(&p_dwlo, g_dwlo);
    __half* sxh  = (__half*)p_xh;
    __half* sxlo = (__half*)p_xlo;
    __half* shid = (__half*)p_hidh;
    float*  sy   = (float*)p_y;
    __half* w1t  = (__half*)p_w1t;
    __half* w2t  = (__half*)p_w2t;
    __half* dwhi = (__half*)p_dwhi;
    __half* dwlo = (__half*)p_dwlo;

    cudaFuncSetAttribute(mgemm_h<true, false, true, true>,
                         cudaFuncAttributeMaxDynamicSharedMemorySize, HSM_TOTAL);
    cudaFuncSetAttribute(mgemm_h<false, true, false, false>,
                         cudaFuncAttributeMaxDynamicSharedMemorySize, HSM_TOTAL);
    cudaFuncSetAttribute(dptc_k,
                         cudaFuncAttributeMaxDynamicSharedMemorySize, DP_TOTAL);

    // 1. zero expert counters
    init_kernel<<<1, 32>>>();

    // 2. x -> fp16 hi/lo; weight transposes
    xsplit_k<<<(T_TOK * D_DIM / 4) / 256, 256>>>(x, sxh, sxlo);
    transpose_hl_k<<<dim3(DP_H / 32, D_DIM / 32, 1), dim3(32, 8)>>>(dp_w1, dwhi, dwlo, D_DIM, DP_H);
    transpose_k<<<dim3(H_DIM / 32, D_DIM / 32, E_EXP), dim3(32, 8)>>>(ew1, w1t, D_DIM, H_DIM);
    transpose_k<<<dim3(D_DIM / 32, H_DIM / 32, E_EXP), dim3(32, 8)>>>(ew2, w2t, H_DIM, D_DIM);

    // 3. dp GEMM on tensor cores (fp16x3 split, 512 thr) + fused entropy
    dptc_k<<<dim3(T_TOK / 128, DP_H / 128), 512, DP_TOTAL>>>(
        sxh, sxlo, dwhi, dwlo, dp_b1, dp_w2);

    // 4. routing (exact fp32 logits + deterministic entropy partial sum)
    route_kernel<<<(T_TOK * 32) / 256, 256>>>(x, dp_b2, gate_w, gate_b);

    // 5. expert GEMM1 (fp16 mma, gathered A): hid = relu(Xh[list] @ W1 + b1) -> fp16
    mgemm_h<true, false, true, true><<<dim3(T_TOK / 128, H_DIM / 256, E_EXP), 512, HSM_TOTAL>>>(
        sxh, 0, D_DIM, w1t, (size_t)D_DIM * H_DIM, eb1, H_DIM,
        shid, (size_t)T_TOK * H_DIM, H_DIM, D_DIM);

    // 6. expert GEMM2 (fp16 mma, scattered C): y[tok] = hid @ W2 + b2 -> fp32
    mgemm_h<false, true, false, false><<<dim3(T_TOK / 128, D_DIM / 256, E_EXP), 512, HSM_TOTAL>>>(
        shid, (size_t)T_TOK * H_DIM, H_DIM, w2t, (size_t)H_DIM * D_DIM, eb2, D_DIM,
        sy, (size_t)T_TOK * D_DIM, D_DIM, H_DIM);

    // 7. weighted combine
    combine_kernel<<<(T_TOK * D_DIM / 4) / 256, 256>>>(out);
}

// round 14
// speedup vs baseline: 1.1285x; 1.0424x over previous
#include <cuda_runtime.h>
#include <cuda.h>
#include <cuda_fp16.h>
#include <math.h>
#include <stdint.h>

#define T_TOK 8192
#define D_DIM 1024
#define H_DIM 2048
#define E_EXP 4
#define DP_H  512

// ---------------- scratch (device globals; no allocations) -------------------
__device__ __half g_xh  [(size_t)T_TOK * D_DIM];           // x hi (fp16)
__device__ __half g_xlo [(size_t)T_TOK * D_DIM];           // x lo (fp16)
__device__ __half g_hidh[(size_t)E_EXP * T_TOK * H_DIM];   // expert hidden fp16
__device__ float  g_y   [(size_t)E_EXP * T_TOK * D_DIM];   // expert outputs
__device__ __half g_w1t [(size_t)E_EXP * D_DIM * H_DIM];   // [E][H][D] K-contig fp16
__device__ __half g_w2t [(size_t)E_EXP * H_DIM * D_DIM];   // [E][D][H] K-contig fp16
__device__ __half g_dwhi[(size_t)DP_H * D_DIM];            // dp_w1^T hi [512][1024]
__device__ __half g_dwlo[(size_t)DP_H * D_DIM];            // dp_w1^T lo
__device__ float  g_entp[4][T_TOK];                        // dp entropy partials
__device__ float  g_dw  [(size_t)T_TOK * E_EXP];
__device__ int    g_cnt [E_EXP];
__device__ int    g_list[(size_t)E_EXP * T_TOK];

// ---------------- helpers ----------------------------------------------------
__device__ __forceinline__ uint32_t smem_to_u32(const void* p) {
    uint32_t a;
    asm("{ .reg .u64 t; cvta.to.shared.u64 t, %1; cvt.u32.u64 %0, t; }" : "=r"(a) : "l"(p));
    return a;
}

#define CPA16(dst, src) \
    asm volatile("cp.async.cg.shared.global [%0], [%1], 16;" :: "r"(dst), "l"(src) : "memory")
#define CPA_COMMIT() asm volatile("cp.async.commit_group;" ::: "memory")
#define CPA_WAIT1()  asm volatile("cp.async.wait_group 1;" ::: "memory")
#define CPA_WAIT2()  asm volatile("cp.async.wait_group 2;" ::: "memory")

#define LDSM_X4(r, addr) \
    asm volatile("ldmatrix.sync.aligned.m8n8.x4.shared.b16 {%0,%1,%2,%3}, [%4];" \
        : "=r"((r)[0]), "=r"((r)[1]), "=r"((r)[2]), "=r"((r)[3]) : "r"(addr))

#define MMA_F16(c, a0, a1, a2, a3, b0, b1) \
    asm volatile("mma.sync.aligned.m16n8k16.row.col.f32.f16.f16.f32 " \
        "{%0,%1,%2,%3}, {%4,%5,%6,%7}, {%8,%9}, {%0,%1,%2,%3};" \
        : "+f"((c)[0]), "+f"((c)[1]), "+f"((c)[2]), "+f"((c)[3]) \
        : "r"(a0), "r"(a1), "r"(a2), "r"(a3), "r"(b0), "r"(b1))

// ---------------- init -------------------------------------------------------
__global__ void init_kernel() {
    if (threadIdx.x < E_EXP) g_cnt[threadIdx.x] = 0;
}

// ---------------- x -> fp16 hi + lo ------------------------------------------
__global__ void xsplit_k(const float* __restrict__ in,
                         __half* __restrict__ hi, __half* __restrict__ lo) {
    size_t i = (size_t)blockIdx.x * blockDim.x + threadIdx.x;
    float4 v = ((const float4*)in)[i];
    __half2 h0 = __floats2half2_rn(v.x, v.y);
    __half2 h1 = __floats2half2_rn(v.z, v.w);
    __half2 l0 = __floats2half2_rn(v.x - __low2float(h0), v.y - __high2float(h0));
    __half2 l1 = __floats2half2_rn(v.z - __low2float(h1), v.w - __high2float(h1));
    __half2 hh[2] = { h0, h1 };
    __half2 ll[2] = { l0, l1 };
    ((uint2*)hi)[i] = *(uint2*)hh;
    ((uint2*)lo)[i] = *(uint2*)ll;
}

// ---------------- transpose: in [z][R][C] f32 -> out [z][C][R] fp16 ----------
// Vectorized half2 stores; store loop remapped so every index is in [0,32):
//   j = tid&15 selects row pair (2j, 2j+1); col = p*16 + (tid>>4).
__global__ void transpose_k(const float* __restrict__ in, __half* __restrict__ out,
                            int R, int C) {
    __shared__ float t[32][33];
    int z = blockIdx.z;
    const float* I = in + (size_t)z * R * C;
    __half* O = out + (size_t)z * R * C;
    int r0 = blockIdx.y * 32, c0 = blockIdx.x * 32;
    int tx = threadIdx.x, ty = threadIdx.y;  // 32 x 8
#pragma unroll
    for (int i = 0; i < 32; i += 8)
        t[ty + i][tx] = I[(size_t)(r0 + ty + i) * C + c0 + tx];
    __syncthreads();
    int tid = ty * 32 + tx;
    int j = tid & 15;            // row pair: rows 2j, 2j+1 (both < 32)
#pragma unroll
    for (int p = 0; p < 2; ++p) {
        int col = p * 16 + (tid >> 4);   // 0..31
        __half2 hv = __floats2half2_rn(t[2 * j][col], t[2 * j + 1][col]);
        *(__half2*)(O + (size_t)(c0 + col) * R + r0 + 2 * j) = hv;
    }
}

// ---------------- transpose with hi/lo split: [R][C] f32 -> [C][R] fp16 x2 ---
__global__ void transpose_hl_k(const float* __restrict__ in,
                               __half* __restrict__ ohi, __half* __restrict__ olo,
                               int R, int C) {
    __shared__ float t[32][33];
    int r0 = blockIdx.y * 32, c0 = blockIdx.x * 32;
    int tx = threadIdx.x, ty = threadIdx.y;  // 32 x 8
#pragma unroll
    for (int i = 0; i < 32; i += 8)
        t[ty + i][tx] = in[(size_t)(r0 + ty + i) * C + c0 + tx];
    __syncthreads();
    int tid = ty * 32 + tx;
    int j = tid & 15;
#pragma unroll
    for (int p = 0; p < 2; ++p) {
        int col = p * 16 + (tid >> 4);
        float v0 = t[2 * j][col];
        float v1 = t[2 * j + 1][col];
        __half h0 = __float2half_rn(v0);
        __half h1 = __float2half_rn(v1);
        __half l0 = __float2half_rn(v0 - __half2float(h0));
        __half l1 = __float2half_rn(v1 - __half2float(h1));
        size_t off = (size_t)(c0 + col) * R + r0 + 2 * j;
        *(__half2*)(ohi + off) = __halves2half2(h0, h1);
        *(__half2*)(olo + off) = __halves2half2(l0, l1);
    }
}

// ---------------- tensor-core fp16x3 dp GEMM + fused entropy (R7 config) -----
// h = relu(X @ W1^T + b1), 3-term split; g_entp[by][t] = sum h*w2 over 128-col
// slab. Block 128x128xk32, 8 warps (2m x 4n), warp tile 64x32, 3 stages.
#define DP_STR  10240              /* one 128x(32h) stream, 80B rows */
#define DP_STAGE (4 * DP_STR)
#define DP_TOTAL (1024 + 3 * DP_STAGE)

__global__ __launch_bounds__(256, 1)
void dptc_k(const __half* __restrict__ Ahi, const __half* __restrict__ Alo,
            const __half* __restrict__ Bhi, const __half* __restrict__ Blo,
            const float* __restrict__ bias, const float* __restrict__ w2)
{
    extern __shared__ __align__(128) char smem[];
    const int m0 = blockIdx.x * 128;
    const int n0 = blockIdx.y * 128;
    const uint32_t sbase = smem_to_u32(smem) + 1024;
    const int tid = threadIdx.x;
    const int lane = tid & 31;
    const int wid = tid >> 5;
    const int wm = wid & 1;
    const int wn = wid >> 1;
    const int K = D_DIM;

    const int arow = tid >> 1;
    const int ah = tid & 1;
    const __half* pAhi = Ahi + (size_t)(m0 + arow) * K + ah * 16;
    const __half* pAlo = Alo + (size_t)(m0 + arow) * K + ah * 16;
    const __half* pBhi = Bhi + (size_t)(n0 + arow) * K + ah * 16;
    const __half* pBlo = Blo + (size_t)(n0 + arow) * K + ah * 16;
    const uint32_t dRow = (uint32_t)arow * 80u + (uint32_t)ah * 32u;

    const int sub = lane & 7;
    const int sel = lane >> 3;
    const uint32_t aOff = (uint32_t)(wm * 64 + (sel & 1) * 8 + sub) * 80u + (uint32_t)(sel >> 1) * 16u;
    const uint32_t bOff = (uint32_t)(wn * 32 + (sel & 1) * 8 + sub) * 80u + (uint32_t)(sel >> 1) * 16u;

    float acc[4][4][4];
#pragma unroll
    for (int i = 0; i < 4; i++)
#pragma unroll
        for (int j = 0; j < 4; j++)
#pragma unroll
            for (int q = 0; q < 4; q++) acc[i][j][q] = 0.f;

    const int nk = K >> 5;

#pragma unroll
    for (int p = 0; p < 2; ++p) {
        const uint32_t so = (uint32_t)p * DP_STAGE;
        const int ko = p * 32;
        CPA16(sbase + so + dRow, pAhi + ko);               CPA16(sbase + so + dRow + 16, pAhi + ko + 8);
        CPA16(sbase + so + DP_STR + dRow, pAlo + ko);      CPA16(sbase + so + DP_STR + dRow + 16, pAlo + ko + 8);
        CPA16(sbase + so + 2 * DP_STR + dRow, pBhi + ko);  CPA16(sbase + so + 2 * DP_STR + dRow + 16, pBhi + ko + 8);
        CPA16(sbase + so + 3 * DP_STR + dRow, pBlo + ko);  CPA16(sbase + so + 3 * DP_STR + dRow + 16, pBlo + ko + 8);
        CPA_COMMIT();
    }

    for (int it = 0; it < nk; ++it) {
        CPA_WAIT1();
        __syncthreads();
        if (it + 2 < nk) {
            const uint32_t so = (uint32_t)((it + 2) % 3) * DP_STAGE;
            const int ko = (it + 2) * 32;
            CPA16(sbase + so + dRow, pAhi + ko);               CPA16(sbase + so + dRow + 16, pAhi + ko + 8);
            CPA16(sbase + so + DP_STR + dRow, pAlo + ko);      CPA16(sbase + so + DP_STR + dRow + 16, pAlo + ko + 8);
            CPA16(sbase + so + 2 * DP_STR + dRow, pBhi + ko);  CPA16(sbase + so + 2 * DP_STR + dRow + 16, pBhi + ko + 8);
            CPA16(sbase + so + 3 * DP_STR + dRow, pBlo + ko);  CPA16(sbase + so + 3 * DP_STR + dRow + 16, pBlo + ko + 8);
            CPA_COMMIT();
        }
        const uint32_t so = (uint32_t)(it % 3) * DP_STAGE;
#pragma unroll
        for (int q = 0; q < 2; ++q) {
            uint32_t ah4[4][4], al4[4][4];
#pragma unroll
            for (int mf = 0; mf < 4; ++mf) {
                LDSM_X4(ah4[mf], sbase + so + aOff + (uint32_t)mf * 1280u + (uint32_t)q * 32u);
                LDSM_X4(al4[mf], sbase + so + DP_STR + aOff + (uint32_t)mf * 1280u + (uint32_t)q * 32u);
            }
#pragma unroll
            for (int p = 0; p < 2; ++p) {
                uint32_t bh[4], bl[4];
                LDSM_X4(bh, sbase + so + 2 * DP_STR + bOff + (uint32_t)p * 1280u + (uint32_t)q * 32u);
                LDSM_X4(bl, sbase + so + 3 * DP_STR + bOff + (uint32_t)p * 1280u + (uint32_t)q * 32u);
#pragma unroll
                for (int mf = 0; mf < 4; ++mf) {
                    MMA_F16(acc[mf][2 * p],     ah4[mf][0], ah4[mf][1], ah4[mf][2], ah4[mf][3], bh[0], bh[2]);
                    MMA_F16(acc[mf][2 * p + 1], ah4[mf][0], ah4[mf][1], ah4[mf][2], ah4[mf][3], bh[1], bh[3]);
                    MMA_F16(acc[mf][2 * p],     ah4[mf][0], ah4[mf][1], ah4[mf][2], ah4[mf][3], bl[0], bl[2]);
                    MMA_F16(acc[mf][2 * p + 1], ah4[mf][0], ah4[mf][1], ah4[mf][2], ah4[mf][3], bl[1], bl[3]);
                    MMA_F16(acc[mf][2 * p],     al4[mf][0], al4[mf][1], al4[mf][2], al4[mf][3], bh[0], bh[2]);
                    MMA_F16(acc[mf][2 * p + 1], al4[mf][0], al4[mf][1], al4[mf][2], al4[mf][3], bh[1], bh[3]);
                }
            }
        }
    }

    // epilogue: relu(+bias) dot w2, block-reduce per row
    __syncthreads();
    float (*red)[17] = (float (*)[17])smem;
    const int g = lane >> 2, tg = lane & 3;
    float rs[4][2];
#pragma unroll
    for (int mf = 0; mf < 4; ++mf)
#pragma unroll
        for (int r2 = 0; r2 < 2; ++r2) rs[mf][r2] = 0.f;
#pragma unroll
    for (int nf = 0; nf < 4; ++nf) {
        int col = n0 + wn * 32 + nf * 8 + 2 * tg;
        float2 bb = *(const float2*)(bias + col);
        float2 ww = *(const float2*)(w2 + col);
#pragma unroll
        for (int mf = 0; mf < 4; ++mf)
#pragma unroll
            for (int r2 = 0; r2 < 2; ++r2) {
                rs[mf][r2] += fmaxf(acc[mf][nf][r2 * 2] + bb.x, 0.f) * ww.x
                            + fmaxf(acc[mf][nf][r2 * 2 + 1] + bb.y, 0.f) * ww.y;
            }
    }
#pragma unroll
    for (int mf = 0; mf < 4; ++mf)
#pragma unroll
        for (int r2 = 0; r2 < 2; ++r2)
            red[wm * 64 + mf * 16 + g + r2 * 8][wn * 4 + tg] = rs[mf][r2];
    __syncthreads();
    if (tid < 128) {
        float s = 0.f;
#pragma unroll
        for (int k = 0; k < 16; k++) s += red[tid][k];
        g_entp[blockIdx.y][m0 + tid] = s;
    }
}

// ---------------- tensor-core fp16 GEMM (expert path, R7 proven config) ------
// Block 128x256xk32, 16 warps (4m x 4n), warp tile 32x64, 4 smem stages.
#define HSM_A   10240              /* 128*80 */
#define HSTAGE  30720              /* A + 256*80 */
#define HSM_TOTAL (1024 + 4 * HSTAGE)

template<bool GATHER_A, bool SCATTER_C, bool RELU, bool OUT_HALF>
__global__ __launch_bounds__(512, 1)
void mgemm_h(const __half* __restrict__ A, size_t A_es, int lda,
             const __half* __restrict__ Bt, size_t B_es,
             const float* __restrict__ bias, int bias_es,
             void* __restrict__ Cv, size_t C_es, int ldc, int K)
{
    extern __shared__ __align__(128) char smem[];
    const int e = blockIdx.z;
    const int M = g_cnt[e];
    const int m0 = blockIdx.x * 128;
    if (m0 >= M) return;
    const int n0 = blockIdx.y * 256;

    const uint32_t sbase = smem_to_u32(smem);
    const int tid = threadIdx.x;
    const int lane = tid & 31;
    const int wid = tid >> 5;
    const int wm = wid & 3;       // 4 warps in m (32 rows each)
    const int wn = wid >> 2;      // 4 warps in n (64 cols each)

    const __half* Ae = A + (size_t)e * A_es;
    const __half* Be = Bt + (size_t)e * B_es;
    const float* be = bias + (size_t)e * bias_es;
    const int* le = g_list + (size_t)e * T_TOK;

    int* rowIdx = (int*)smem;
    if (tid < 128) {
        int m = m0 + tid;
        rowIdx[tid] = (m < M) ? le[m] : 0;
    }
    __syncthreads();

    // cp.async mapping: A = 1 chunk/thread, B = 2 chunks/thread (16B chunks)
    const int arow = tid >> 2;                  // 0..127
    const int ach  = tid & 3;                   // 0..3
    int ar = GATHER_A ? rowIdx[arow] : (m0 + arow);
    const __half* Aptr = Ae + (size_t)ar * lda + ach * 8;
    const uint32_t dA = sbase + 1024 + (uint32_t)arow * 80u + (uint32_t)ach * 16u;

    const int br0 = tid >> 2;                   // B rows 0..127
    const int br1 = br0 + 128;                  // B rows 128..255
    const int bs  = tid & 3;
    const __half* Bp0 = Be + (size_t)(n0 + br0) * K + bs * 8;
    const __half* Bp1 = Be + (size_t)(n0 + br1) * K + bs * 8;
    const uint32_t dB0 = sbase + 1024 + HSM_A + (uint32_t)br0 * 80u + (uint32_t)bs * 16u;
    const uint32_t dB1 = sbase + 1024 + HSM_A + (uint32_t)br1 * 80u + (uint32_t)bs * 16u;

    // LDSM bases
    const int sub = lane & 7;
    const int sel = lane >> 3;
    const uint32_t aL = sbase + 1024 +
        (uint32_t)(wm * 32 + (sel & 1) * 8 + sub) * 80u + (uint32_t)(sel >> 1) * 16u;
    const uint32_t bL = sbase + 1024 + HSM_A +
        (uint32_t)(wn * 64 + (sel & 1) * 8 + sub) * 80u + (uint32_t)(sel >> 1) * 16u;

    float acc[2][8][4];
#pragma unroll
    for (int i = 0; i < 2; i++)
#pragma unroll
        for (int j = 0; j < 8; j++)
#pragma unroll
            for (int q = 0; q < 4; q++) acc[i][j][q] = 0.f;

    const int nk = K >> 5;

    // prologue: tiles 0..2 into stages 0..2
#pragma unroll
    for (int p = 0; p < 3; ++p) {
        const uint32_t so = (uint32_t)p * HSTAGE;
        CPA16(dA + so, Aptr + p * 32);
        CPA16(dB0 + so, Bp0 + p * 32);
        CPA16(dB1 + so, Bp1 + p * 32);
        CPA_COMMIT();
    }

    for (int it = 0; it < nk; ++it) {
        CPA_WAIT2();
        __syncthreads();
        if (it + 3 < nk) {
            const uint32_t so = (uint32_t)((it + 3) & 3) * HSTAGE;
            CPA16(dA + so, Aptr + (size_t)(it + 3) * 32);
            CPA16(dB0 + so, Bp0 + (size_t)(it + 3) * 32);
            CPA16(dB1 + so, Bp1 + (size_t)(it + 3) * 32);
            CPA_COMMIT();
        }
        const uint32_t so = (uint32_t)(it & 3) * HSTAGE;
#pragma unroll
        for (int q = 0; q < 2; ++q) {
            uint32_t af[2][4];
#pragma unroll
            for (int mf = 0; mf < 2; ++mf)
                LDSM_X4(af[mf], aL + so + (uint32_t)mf * 1280u + (uint32_t)q * 32u);
#pragma unroll
            for (int p = 0; p < 4; ++p) {
                uint32_t bf[4];
                LDSM_X4(bf, bL + so + (uint32_t)p * 1280u + (uint32_t)q * 32u);
#pragma unroll
                for (int mf = 0; mf < 2; ++mf) {
                    MMA_F16(acc[mf][2 * p],     af[mf][0], af[mf][1], af[mf][2], af[mf][3], bf[0], bf[2]);
                    MMA_F16(acc[mf][2 * p + 1], af[mf][0], af[mf][1], af[mf][2], af[mf][3], bf[1], bf[3]);
                }
            }
        }
    }

    // epilogue
    const int g = lane >> 2, tg = lane & 3;
#pragma unroll
    for (int mf = 0; mf < 2; ++mf) {
#pragma unroll
        for (int r2 = 0; r2 < 2; ++r2) {
            int mloc = wm * 32 + mf * 16 + g + r2 * 8;
            if (m0 + mloc >= M) continue;
            int orow = SCATTER_C ? rowIdx[mloc] : (m0 + mloc);
#pragma unroll
            for (int nf = 0; nf < 8; ++nf) {
                int col = wn * 64 + nf * 8 + 2 * tg;
                float2 bb = *(const float2*)(be + n0 + col);
                float vx = acc[mf][nf][r2 * 2] + bb.x;
                float vy = acc[mf][nf][r2 * 2 + 1] + bb.y;
                if (RELU) { vx = fmaxf(vx, 0.f); vy = fmaxf(vy, 0.f); }
                if (OUT_HALF) {
                    __half* dst = (__half*)Cv + (size_t)e * C_es + (size_t)orow * ldc + n0 + col;
                    *(__half2*)dst = __floats2half2_rn(vx, vy);
                } else {
                    float* dst = (float*)Cv + (size_t)e * C_es + (size_t)orow * ldc + n0 + col;
                    float2 v; v.x = vx; v.y = vy;
                    *(float2*)dst = v;
                }
            }
        }
    }
}

// ---------------- routing ----------------------------------------------------
__global__ void route_kernel(const float* __restrict__ x,
                             const float* __restrict__ dp_b2,
                             const float* __restrict__ gate_w,
                             const float* __restrict__ gate_b)
{
    int warp = (blockIdx.x * blockDim.x + threadIdx.x) >> 5;
    int lane = threadIdx.x & 31;
    if (warp >= T_TOK) return;

    const float* xr = x + (size_t)warp * D_DIM;
    float l0 = 0.f, l1 = 0.f, l2 = 0.f, l3 = 0.f;
    for (int j = lane; j < D_DIM; j += 32) {
        float xv = xr[j];
        float4 gw = *(const float4*)(gate_w + (size_t)j * 4);
        l0 += xv * gw.x; l1 += xv * gw.y; l2 += xv * gw.z; l3 += xv * gw.w;
    }
#pragma unroll
    for (int off = 16; off; off >>= 1) {
        l0 += __shfl_down_sync(0xffffffffu, l0, off);
        l1 += __shfl_down_sync(0xffffffffu, l1, off);
        l2 += __shfl_down_sync(0xffffffffu, l2, off);
        l3 += __shfl_down_sync(0xffffffffu, l3, off);
    }
    if (lane != 0) return;

    float ent = ((g_entp[0][warp] + g_entp[1][warp]) +
                 (g_entp[2][warp] + g_entp[3][warp])) + dp_b2[0];
    ent = fmaxf(ent, 0.f) + log1pf(expf(-fabsf(ent)));
    float norm = fminf(fmaxf((ent - 0.5f) / 1.5f, 0.f), 1.f);
    int k = (int)rintf(1.0f + norm * 3.0f);
    k = max(1, min(E_EXP, k));

    float lg[4] = { l0 + gate_b[0], l1 + gate_b[1], l2 + gate_b[2], l3 + gate_b[3] };
    int idx[4] = { 0, 1, 2, 3 };
#pragma unroll
    for (int a = 0; a < 3; a++) {
        int best = a;
#pragma unroll
        for (int b = a + 1; b < 4; b++)
            if (lg[idx[b]] > lg[idx[best]]) best = b;
        int t = idx[a]; idx[a] = idx[best]; idx[best] = t;
    }
    float mx = lg[idx[0]];
    float w[4]; float wsum = 0.f;
#pragma unroll
    for (int j = 0; j < 4; j++) {
        w[j] = (j < k) ? expf(lg[idx[j]] - mx) : 0.f;
        wsum += w[j];
    }
    float inv = 1.f / wsum;
    float dw[4] = { 0.f, 0.f, 0.f, 0.f };
#pragma unroll
    for (int j = 0; j < 4; j++)
        if (j < k) dw[idx[j]] = w[j] * inv;
#pragma unroll
    for (int e2 = 0; e2 < 4; e2++) g_dw[(size_t)warp * 4 + e2] = dw[e2];

    for (int j = 0; j < k; j++) {
        int ex = idx[j];
        int p = atomicAdd(&g_cnt[ex], 1);
        g_list[(size_t)ex * T_TOK + p] = warp;
    }
}

// ---------------- combine ----------------------------------------------------
__global__ void combine_kernel(float* __restrict__ out)
{
    const size_t P = (size_t)T_TOK * D_DIM / 4;
    size_t i = (size_t)blockIdx.x * blockDim.x + threadIdx.x;
    if (i >= P) return;
    int t = (int)(i >> 8);
    float w0 = g_dw[(size_t)t * 4 + 0];
    float w1 = g_dw[(size_t)t * 4 + 1];
    float w2 = g_dw[(size_t)t * 4 + 2];
    float w3 = g_dw[(size_t)t * 4 + 3];
    const float4* y4 = (const float4*)g_y;
    float4 o = make_float4(0.f, 0.f, 0.f, 0.f);
    if (w0 != 0.f) { float4 a = y4[i];
        o.x += w0 * a.x; o.y += w0 * a.y; o.z += w0 * a.z; o.w += w0 * a.w; }
    if (w1 != 0.f) { float4 a = y4[P + i];
        o.x += w1 * a.x; o.y += w1 * a.y; o.z += w1 * a.z; o.w += w1 * a.w; }
    if (w2 != 0.f) { float4 a = y4[2 * P + i];
        o.x += w2 * a.x; o.y += w2 * a.y; o.z += w2 * a.z; o.w += w2 * a.w; }
    if (w3 != 0.f) { float4 a = y4[3 * P + i];
        o.x += w3 * a.x; o.y += w3 * a.y; o.z += w3 * a.z; o.w += w3 * a.w; }
    ((float4*)out)[i] = o;
}

// ---------------- launch -----------------------------------------------------
extern "C" void kernel_launch(void* const* d_in, const int* in_sizes, int n_in,
                              void* d_out, int out_size)
{
    (void)in_sizes; (void)n_in; (void)out_size;
    const float* x      = (const float*)d_in[0];
    const float* gate_w = (const float*)d_in[1];
    const float* gate_b = (const float*)d_in[2];
    const float* dp_w1  = (const float*)d_in[3];
    const float* dp_b1  = (const float*)d_in[4];
    const float* dp_w2  = (const float*)d_in[5];
    const float* dp_b2  = (const float*)d_in[6];
    const float* ew1    = (const float*)d_in[7];
    const float* eb1    = (const float*)d_in[8];
    const float* ew2    = (const float*)d_in[9];
    const float* eb2    = (const float*)d_in[10];
    float* out = (float*)d_out;

    void *p_xh, *p_xlo, *p_hidh, *p_y, *p_w1t, *p_w2t, *p_dwhi, *p_dwlo;
    cudaGetSymbolAddress(&p_xh,   g_xh);
    cudaGetSymbolAddress(&p_xlo,  g_xlo);
    cudaGetSymbolAddress(&p_hidh, g_hidh);
    cudaGetSymbolAddress(&p_y,    g_y);
    cudaGetSymbolAddress(&p_w1t,  g_w1t);
    cudaGetSymbolAddress(&p_w2t,  g_w2t);
    cudaGetSymbolAddress(&p_dwhi, g_dwhi);
    cudaGetSymbolAddress(&p_dwlo, g_dwlo);
    __half* sxh  = (__half*)p_xh;
    __half* sxlo = (__half*)p_xlo;
    __half* shid = (__half*)p_hidh;
    float*  sy   = (float*)p_y;
    __half* w1t  = (__half*)p_w1t;
    __half* w2t  = (__half*)p_w2t;
    __half* dwhi = (__half*)p_dwhi;
    __half* dwlo = (__half*)p_dwlo;

    cudaFuncSetAttribute(mgemm_h<true, false, true, true>,
                         cudaFuncAttributeMaxDynamicSharedMemorySize, HSM_TOTAL);
    cudaFuncSetAttribute(mgemm_h<false, true, false, false>,
                         cudaFuncAttributeMaxDynamicSharedMemorySize, HSM_TOTAL);
    cudaFuncSetAttribute(dptc_k,
                         cudaFuncAttributeMaxDynamicSharedMemorySize, DP_TOTAL);

    // 1. zero expert counters
    init_kernel<<<1, 32>>>();

    // 2. x -> fp16 hi/lo; weight transposes
    xsplit_k<<<(T_TOK * D_DIM / 4) / 256, 256>>>(x, sxh, sxlo);
    transpose_hl_k<<<dim3(DP_H / 32, D_DIM / 32, 1), dim3(32, 8)>>>(dp_w1, dwhi, dwlo, D_DIM, DP_H);
    transpose_k<<<dim3(H_DIM / 32, D_DIM / 32, E_EXP), dim3(32, 8)>>>(ew1, w1t, D_DIM, H_DIM);
    transpose_k<<<dim3(D_DIM / 32, H_DIM / 32, E_EXP), dim3(32, 8)>>>(ew2, w2t, H_DIM, D_DIM);

    // 3. dp GEMM on tensor cores (fp16x3 split, R7 256-thr config) + entropy
    dptc_k<<<dim3(T_TOK / 128, DP_H / 128), 256, DP_TOTAL>>>(
        sxh, sxlo, dwhi, dwlo, dp_b1, dp_w2);

    // 4. routing (exact fp32 logits + deterministic entropy partial sum)
    route_kernel<<<(T_TOK * 32) / 256, 256>>>(x, dp_b2, gate_w, gate_b);

    // 5. expert GEMM1 (fp16 mma, gathered A): hid = relu(Xh[list] @ W1 + b1) -> fp16
    mgemm_h<true, false, true, true><<<dim3(T_TOK / 128, H_DIM / 256, E_EXP), 512, HSM_TOTAL>>>(
        sxh, 0, D_DIM, w1t, (size_t)D_DIM * H_DIM, eb1, H_DIM,
        shid, (size_t)T_TOK * H_DIM, H_DIM, D_DIM);

    // 6. expert GEMM2 (fp16 mma, scattered C): y[tok] = hid @ W2 + b2 -> fp32
    mgemm_h<false, true, false, false><<<dim3(T_TOK / 128, D_DIM / 256, E_EXP), 512, HSM_TOTAL>>>(
        shid, (size_t)T_TOK * H_DIM, H_DIM, w2t, (size_t)H_DIM * D_DIM, eb2, D_DIM,
        sy, (size_t)T_TOK * D_DIM, D_DIM, H_DIM);

    // 7. weighted combine
    combine_kernel<<<(T_TOK * D_DIM / 4) / 256, 256>>>(out);
}

// round 17
// speedup vs baseline: 1.1345x; 1.0052x over previous
#include <cuda_runtime.h>
#include <cuda.h>
#include <cuda_fp16.h>
#include <math.h>
#include <stdint.h>

#define T_TOK 8192
#define D_DIM 1024
#define H_DIM 2048
#define E_EXP 4
#define DP_H  512

// ---------------- scratch (device globals; no allocations) -------------------
__device__ __half g_xh  [(size_t)T_TOK * D_DIM];           // x hi (fp16)
__device__ __half g_xlo [(size_t)T_TOK * D_DIM];           // x lo (fp16)
__device__ __half g_hidh[(size_t)E_EXP * T_TOK * H_DIM];   // expert hidden fp16
__device__ float  g_y   [(size_t)E_EXP * T_TOK * D_DIM];   // expert outputs
__device__ __half g_w1t [(size_t)E_EXP * D_DIM * H_DIM];   // [E][H][D] K-contig fp16
__device__ __half g_w2t [(size_t)E_EXP * H_DIM * D_DIM];   // [E][D][H] K-contig fp16
__device__ __half g_dwhi[(size_t)DP_H * D_DIM];            // dp_w1^T hi [512][1024]
__device__ __half g_dwlo[(size_t)DP_H * D_DIM];            // dp_w1^T lo
__device__ float  g_entp[4][T_TOK];                        // dp entropy partials
__device__ float  g_dw  [(size_t)T_TOK * E_EXP];
__device__ int    g_cnt [E_EXP];
__device__ int    g_list[(size_t)E_EXP * T_TOK];

// ---------------- helpers ----------------------------------------------------
__device__ __forceinline__ uint32_t smem_to_u32(const void* p) {
    uint32_t a;
    asm("{ .reg .u64 t; cvta.to.shared.u64 t, %1; cvt.u32.u64 %0, t; }" : "=r"(a) : "l"(p));
    return a;
}

#define CPA16(dst, src) \
    asm volatile("cp.async.cg.shared.global [%0], [%1], 16;" :: "r"(dst), "l"(src) : "memory")
#define CPA_COMMIT() asm volatile("cp.async.commit_group;" ::: "memory")
#define CPA_WAIT1()  asm volatile("cp.async.wait_group 1;" ::: "memory")
#define CPA_WAIT2()  asm volatile("cp.async.wait_group 2;" ::: "memory")

#define LDSM_X4(r, addr) \
    asm volatile("ldmatrix.sync.aligned.m8n8.x4.shared.b16 {%0,%1,%2,%3}, [%4];" \
        : "=r"((r)[0]), "=r"((r)[1]), "=r"((r)[2]), "=r"((r)[3]) : "r"(addr))

#define MMA_F16(c, a0, a1, a2, a3, b0, b1) \
    asm volatile("mma.sync.aligned.m16n8k16.row.col.f32.f16.f16.f32 " \
        "{%0,%1,%2,%3}, {%4,%5,%6,%7}, {%8,%9}, {%0,%1,%2,%3};" \
        : "+f"((c)[0]), "+f"((c)[1]), "+f"((c)[2]), "+f"((c)[3]) \
        : "r"(a0), "r"(a1), "r"(a2), "r"(a3), "r"(b0), "r"(b1))

// ---------------- init -------------------------------------------------------
__global__ void init_kernel() {
    if (threadIdx.x < E_EXP) g_cnt[threadIdx.x] = 0;
}

// ---------------- x -> fp16 hi + lo ------------------------------------------
__global__ void xsplit_k(const float* __restrict__ in,
                         __half* __restrict__ hi, __half* __restrict__ lo) {
    size_t i = (size_t)blockIdx.x * blockDim.x + threadIdx.x;
    float4 v = ((const float4*)in)[i];
    __half2 h0 = __floats2half2_rn(v.x, v.y);
    __half2 h1 = __floats2half2_rn(v.z, v.w);
    __half2 l0 = __floats2half2_rn(v.x - __low2float(h0), v.y - __high2float(h0));
    __half2 l1 = __floats2half2_rn(v.z - __low2float(h1), v.w - __high2float(h1));
    __half2 hh[2] = { h0, h1 };
    __half2 ll[2] = { l0, l1 };
    ((uint2*)hi)[i] = *(uint2*)hh;
    ((uint2*)lo)[i] = *(uint2*)ll;
}

// ---------------- transpose: in [z][R][C] f32 -> out [z][C][R] fp16 ----------
// Vectorized half2 stores; j = tid&15 -> row pair (2j,2j+1), col = p*16+(tid>>4)
__global__ void transpose_k(const float* __restrict__ in, __half* __restrict__ out,
                            int R, int C) {
    __shared__ float t[32][33];
    int z = blockIdx.z;
    const float* I = in + (size_t)z * R * C;
    __half* O = out + (size_t)z * R * C;
    int r0 = blockIdx.y * 32, c0 = blockIdx.x * 32;
    int tx = threadIdx.x, ty = threadIdx.y;  // 32 x 8
#pragma unroll
    for (int i = 0; i < 32; i += 8)
        t[ty + i][tx] = I[(size_t)(r0 + ty + i) * C + c0 + tx];
    __syncthreads();
    int tid = ty * 32 + tx;
    int j = tid & 15;
#pragma unroll
    for (int p = 0; p < 2; ++p) {
        int col = p * 16 + (tid >> 4);
        __half2 hv = __floats2half2_rn(t[2 * j][col], t[2 * j + 1][col]);
        *(__half2*)(O + (size_t)(c0 + col) * R + r0 + 2 * j) = hv;
    }
}

// ---------------- transpose with hi/lo split: [R][C] f32 -> [C][R] fp16 x2 ---
__global__ void transpose_hl_k(const float* __restrict__ in,
                               __half* __restrict__ ohi, __half* __restrict__ olo,
                               int R, int C) {
    __shared__ float t[32][33];
    int r0 = blockIdx.y * 32, c0 = blockIdx.x * 32;
    int tx = threadIdx.x, ty = threadIdx.y;  // 32 x 8
#pragma unroll
    for (int i = 0; i < 32; i += 8)
        t[ty + i][tx] = in[(size_t)(r0 + ty + i) * C + c0 + tx];
    __syncthreads();
    int tid = ty * 32 + tx;
    int j = tid & 15;
#pragma unroll
    for (int p = 0; p < 2; ++p) {
        int col = p * 16 + (tid >> 4);
        float v0 = t[2 * j][col];
        float v1 = t[2 * j + 1][col];
        __half h0 = __float2half_rn(v0);
        __half h1 = __float2half_rn(v1);
        __half l0 = __float2half_rn(v0 - __half2float(h0));
        __half l1 = __float2half_rn(v1 - __half2float(h1));
        size_t off = (size_t)(c0 + col) * R + r0 + 2 * j;
        *(__half2*)(ohi + off) = __halves2half2(h0, h1);
        *(__half2*)(olo + off) = __halves2half2(l0, l1);
    }
}

// ---------------- tensor-core fp16x3 dp GEMM + fused entropy (R7 config) -----
#define DP_STR  10240              /* one 128x(32h) stream, 80B rows */
#define DP_STAGE (4 * DP_STR)
#define DP_TOTAL (1024 + 3 * DP_STAGE)

__global__ __launch_bounds__(256, 1)
void dptc_k(const __half* __restrict__ Ahi, const __half* __restrict__ Alo,
            const __half* __restrict__ Bhi, const __half* __restrict__ Blo,
            const float* __restrict__ bias, const float* __restrict__ w2)
{
    extern __shared__ __align__(128) char smem[];
    const int m0 = blockIdx.x * 128;
    const int n0 = blockIdx.y * 128;
    const uint32_t sbase = smem_to_u32(smem) + 1024;
    const int tid = threadIdx.x;
    const int lane = tid & 31;
    const int wid = tid >> 5;
    const int wm = wid & 1;
    const int wn = wid >> 1;
    const int K = D_DIM;

    const int arow = tid >> 1;
    const int ah = tid & 1;
    const __half* pAhi = Ahi + (size_t)(m0 + arow) * K + ah * 16;
    const __half* pAlo = Alo + (size_t)(m0 + arow) * K + ah * 16;
    const __half* pBhi = Bhi + (size_t)(n0 + arow) * K + ah * 16;
    const __half* pBlo = Blo + (size_t)(n0 + arow) * K + ah * 16;
    const uint32_t dRow = (uint32_t)arow * 80u + (uint32_t)ah * 32u;

    const int sub = lane & 7;
    const int sel = lane >> 3;
    const uint32_t aOff = (uint32_t)(wm * 64 + (sel & 1) * 8 + sub) * 80u + (uint32_t)(sel >> 1) * 16u;
    const uint32_t bOff = (uint32_t)(wn * 32 + (sel & 1) * 8 + sub) * 80u + (uint32_t)(sel >> 1) * 16u;

    float acc[4][4][4];
#pragma unroll
    for (int i = 0; i < 4; i++)
#pragma unroll
        for (int j = 0; j < 4; j++)
#pragma unroll
            for (int q = 0; q < 4; q++) acc[i][j][q] = 0.f;

    const int nk = K >> 5;

#pragma unroll
    for (int p = 0; p < 2; ++p) {
        const uint32_t so = (uint32_t)p * DP_STAGE;
        const int ko = p * 32;
        CPA16(sbase + so + dRow, pAhi + ko);               CPA16(sbase + so + dRow + 16, pAhi + ko + 8);
        CPA16(sbase + so + DP_STR + dRow, pAlo + ko);      CPA16(sbase + so + DP_STR + dRow + 16, pAlo + ko + 8);
        CPA16(sbase + so + 2 * DP_STR + dRow, pBhi + ko);  CPA16(sbase + so + 2 * DP_STR + dRow + 16, pBhi + ko + 8);
        CPA16(sbase + so + 3 * DP_STR + dRow, pBlo + ko);  CPA16(sbase + so + 3 * DP_STR + dRow + 16, pBlo + ko + 8);
        CPA_COMMIT();
    }

    for (int it = 0; it < nk; ++it) {
        CPA_WAIT1();
        __syncthreads();
        if (it + 2 < nk) {
            const uint32_t so = (uint32_t)((it + 2) % 3) * DP_STAGE;
            const int ko = (it + 2) * 32;
            CPA16(sbase + so + dRow, pAhi + ko);               CPA16(sbase + so + dRow + 16, pAhi + ko + 8);
            CPA16(sbase + so + DP_STR + dRow, pAlo + ko);      CPA16(sbase + so + DP_STR + dRow + 16, pAlo + ko + 8);
            CPA16(sbase + so + 2 * DP_STR + dRow, pBhi + ko);  CPA16(sbase + so + 2 * DP_STR + dRow + 16, pBhi + ko + 8);
            CPA16(sbase + so + 3 * DP_STR + dRow, pBlo + ko);  CPA16(sbase + so + 3 * DP_STR + dRow + 16, pBlo + ko + 8);
            CPA_COMMIT();
        }
        const uint32_t so = (uint32_t)(it % 3) * DP_STAGE;
#pragma unroll
        for (int q = 0; q < 2; ++q) {
            uint32_t ah4[4][4], al4[4][4];
#pragma unroll
            for (int mf = 0; mf < 4; ++mf) {
                LDSM_X4(ah4[mf], sbase + so + aOff + (uint32_t)mf * 1280u + (uint32_t)q * 32u);
                LDSM_X4(al4[mf], sbase + so + DP_STR + aOff + (uint32_t)mf * 1280u + (uint32_t)q * 32u);
            }
#pragma unroll
            for (int p = 0; p < 2; ++p) {
                uint32_t bh[4], bl[4];
                LDSM_X4(bh, sbase + so + 2 * DP_STR + bOff + (uint32_t)p * 1280u + (uint32_t)q * 32u);
                LDSM_X4(bl, sbase + so + 3 * DP_STR + bOff + (uint32_t)p * 1280u + (uint32_t)q * 32u);
#pragma unroll
                for (int mf = 0; mf < 4; ++mf) {
                    MMA_F16(acc[mf][2 * p],     ah4[mf][0], ah4[mf][1], ah4[mf][2], ah4[mf][3], bh[0], bh[2]);
                    MMA_F16(acc[mf][2 * p + 1], ah4[mf][0], ah4[mf][1], ah4[mf][2], ah4[mf][3], bh[1], bh[3]);
                    MMA_F16(acc[mf][2 * p],     ah4[mf][0], ah4[mf][1], ah4[mf][2], ah4[mf][3], bl[0], bl[2]);
                    MMA_F16(acc[mf][2 * p + 1], ah4[mf][0], ah4[mf][1], ah4[mf][2], ah4[mf][3], bl[1], bl[3]);
                    MMA_F16(acc[mf][2 * p],     al4[mf][0], al4[mf][1], al4[mf][2], al4[mf][3], bh[0], bh[2]);
                    MMA_F16(acc[mf][2 * p + 1], al4[mf][0], al4[mf][1], al4[mf][2], al4[mf][3], bh[1], bh[3]);
                }
            }
        }
    }

    __syncthreads();
    float (*red)[17] = (float (*)[17])smem;
    const int g = lane >> 2, tg = lane & 3;
    float rs[4][2];
#pragma unroll
    for (int mf = 0; mf < 4; ++mf)
#pragma unroll
        for (int r2 = 0; r2 < 2; ++r2) rs[mf][r2] = 0.f;
#pragma unroll
    for (int nf = 0; nf < 4; ++nf) {
        int col = n0 + wn * 32 + nf * 8 + 2 * tg;
        float2 bb = *(const float2*)(bias + col);
        float2 ww = *(const float2*)(w2 + col);
#pragma unroll
        for (int mf = 0; mf < 4; ++mf)
#pragma unroll
            for (int r2 = 0; r2 < 2; ++r2) {
                rs[mf][r2] += fmaxf(acc[mf][nf][r2 * 2] + bb.x, 0.f) * ww.x
                            + fmaxf(acc[mf][nf][r2 * 2 + 1] + bb.y, 0.f) * ww.y;
            }
    }
#pragma unroll
    for (int mf = 0; mf < 4; ++mf)
#pragma unroll
        for (int r2 = 0; r2 < 2; ++r2)
            red[wm * 64 + mf * 16 + g + r2 * 8][wn * 4 + tg] = rs[mf][r2];
    __syncthreads();
    if (tid < 128) {
        float s = 0.f;
#pragma unroll
        for (int k = 0; k < 16; k++) s += red[tid][k];
        g_entp[blockIdx.y][m0 + tid] = s;
    }
}

// ---------------- tensor-core fp16 GEMM (expert path, R7 proven config) ------
// Block 128x256xk32, 16 warps (4m x 4n), warp tile 32x64, 4 smem stages.
// FUSE_OUT (GEMM2 only): rows whose routing weight is exactly 1.0 (k=1 tokens)
// are written straight to the final output — bitwise identical to combine's
// 1.0*y, and combine skips those tokens.
#define HSM_A   10240              /* 128*80 */
#define HSTAGE  30720              /* A + 256*80 */
#define HSM_TOTAL (1024 + 4 * HSTAGE)

template<bool GATHER_A, bool SCATTER_C, bool RELU, bool OUT_HALF, bool FUSE_OUT>
__global__ __launch_bounds__(512, 1)
void mgemm_h(const __half* __restrict__ A, size_t A_es, int lda,
             const __half* __restrict__ Bt, size_t B_es,
             const float* __restrict__ bias, int bias_es,
             void* __restrict__ Cv, size_t C_es, int ldc, int K,
             float* __restrict__ OutF)
{
    extern __shared__ __align__(128) char smem[];
    const int e = blockIdx.z;
    const int M = g_cnt[e];
    const int m0 = blockIdx.x * 128;
    if (m0 >= M) return;
    const int n0 = blockIdx.y * 256;

    const uint32_t sbase = smem_to_u32(smem);
    const int tid = threadIdx.x;
    const int lane = tid & 31;
    const int wid = tid >> 5;
    const int wm = wid & 3;       // 4 warps in m (32 rows each)
    const int wn = wid >> 2;      // 4 warps in n (64 cols each)

    const __half* Ae = A + (size_t)e * A_es;
    const __half* Be = Bt + (size_t)e * B_es;
    const float* be = bias + (size_t)e * bias_es;
    const int* le = g_list + (size_t)e * T_TOK;

    int* rowIdx = (int*)smem;
    if (tid < 128) {
        int m = m0 + tid;
        rowIdx[tid] = (m < M) ? le[m] : 0;
    }
    __syncthreads();

    // cp.async mapping: A = 1 chunk/thread, B = 2 chunks/thread (16B chunks)
    const int arow = tid >> 2;                  // 0..127
    const int ach  = tid & 3;                   // 0..3
    int ar = GATHER_A ? rowIdx[arow] : (m0 + arow);
    const __half* Aptr = Ae + (size_t)ar * lda + ach * 8;
    const uint32_t dA = sbase + 1024 + (uint32_t)arow * 80u + (uint32_t)ach * 16u;

    const int br0 = tid >> 2;                   // B rows 0..127
    const int br1 = br0 + 128;                  // B rows 128..255
    const int bs  = tid & 3;
    const __half* Bp0 = Be + (size_t)(n0 + br0) * K + bs * 8;
    const __half* Bp1 = Be + (size_t)(n0 + br1) * K + bs * 8;
    const uint32_t dB0 = sbase + 1024 + HSM_A + (uint32_t)br0 * 80u + (uint32_t)bs * 16u;
    const uint32_t dB1 = sbase + 1024 + HSM_A + (uint32_t)br1 * 80u + (uint32_t)bs * 16u;

    // LDSM bases
    const int sub = lane & 7;
    const int sel = lane >> 3;
    const uint32_t aL = sbase + 1024 +
        (uint32_t)(wm * 32 + (sel & 1) * 8 + sub) * 80u + (uint32_t)(sel >> 1) * 16u;
    const uint32_t bL = sbase + 1024 + HSM_A +
        (uint32_t)(wn * 64 + (sel & 1) * 8 + sub) * 80u + (uint32_t)(sel >> 1) * 16u;

    float acc[2][8][4];
#pragma unroll
    for (int i = 0; i < 2; i++)
#pragma unroll
        for (int j = 0; j < 8; j++)
#pragma unroll
            for (int q = 0; q < 4; q++) acc[i][j][q] = 0.f;

    const int nk = K >> 5;

    // prologue: tiles 0..2 into stages 0..2
#pragma unroll
    for (int p = 0; p < 3; ++p) {
        const uint32_t so = (uint32_t)p * HSTAGE;
        CPA16(dA + so, Aptr + p * 32);
        CPA16(dB0 + so, Bp0 + p * 32);
        CPA16(dB1 + so, Bp1 + p * 32);
        CPA_COMMIT();
    }

    for (int it = 0; it < nk; ++it) {
        CPA_WAIT2();
        __syncthreads();
        if (it + 3 < nk) {
            const uint32_t so = (uint32_t)((it + 3) & 3) * HSTAGE;
            CPA16(dA + so, Aptr + (size_t)(it + 3) * 32);
            CPA16(dB0 + so, Bp0 + (size_t)(it + 3) * 32);
            CPA16(dB1 + so, Bp1 + (size_t)(it + 3) * 32);
            CPA_COMMIT();
        }
        const uint32_t so = (uint32_t)(it & 3) * HSTAGE;
#pragma unroll
        for (int q = 0; q < 2; ++q) {
            uint32_t af[2][4];
#pragma unroll
            for (int mf = 0; mf < 2; ++mf)
                LDSM_X4(af[mf], aL + so + (uint32_t)mf * 1280u + (uint32_t)q * 32u);
#pragma unroll
            for (int p = 0; p < 4; ++p) {
                uint32_t bf[4];
                LDSM_X4(bf, bL + so + (uint32_t)p * 1280u + (uint32_t)q * 32u);
#pragma unroll
                for (int mf = 0; mf < 2; ++mf) {
                    MMA_F16(acc[mf][2 * p],     af[mf][0], af[mf][1], af[mf][2], af[mf][3], bf[0], bf[2]);
                    MMA_F16(acc[mf][2 * p + 1], af[mf][0], af[mf][1], af[mf][2], af[mf][3], bf[1], bf[3]);
                }
            }
        }
    }

    // epilogue
    const int g = lane >> 2, tg = lane & 3;
#pragma unroll
    for (int mf = 0; mf < 2; ++mf) {
#pragma unroll
        for (int r2 = 0; r2 < 2; ++r2) {
            int mloc = wm * 32 + mf * 16 + g + r2 * 8;
            if (m0 + mloc >= M) continue;
            int orow = SCATTER_C ? rowIdx[mloc] : (m0 + mloc);
            float* fbase;
            if (OUT_HALF) {
                fbase = nullptr;
            } else if (FUSE_OUT) {
                float w = g_dw[(size_t)orow * 4 + e];
                fbase = (w == 1.0f) ? (OutF + (size_t)orow * ldc)
                                    : ((float*)Cv + (size_t)e * C_es + (size_t)orow * ldc);
            } else {
                fbase = (float*)Cv + (size_t)e * C_es + (size_t)orow * ldc;
            }
#pragma unroll
            for (int nf = 0; nf < 8; ++nf) {
                int col = wn * 64 + nf * 8 + 2 * tg;
                float2 bb = *(const float2*)(be + n0 + col);
                float vx = acc[mf][nf][r2 * 2] + bb.x;
                float vy = acc[mf][nf][r2 * 2 + 1] + bb.y;
                if (RELU) { vx = fmaxf(vx, 0.f); vy = fmaxf(vy, 0.f); }
                if (OUT_HALF) {
                    __half* dst = (__half*)Cv + (size_t)e * C_es + (size_t)orow * ldc + n0 + col;
                    *(__half2*)dst = __floats2half2_rn(vx, vy);
                } else {
                    float2 v; v.x = vx; v.y = vy;
                    *(float2*)(fbase + n0 + col) = v;
                }
            }
        }
    }
}

// ---------------- routing ----------------------------------------------------
__global__ void route_kernel(const float* __restrict__ x,
                             const float* __restrict__ dp_b2,
                             const float* __restrict__ gate_w,
                             const float* __restrict__ gate_b)
{
    int warp = (blockIdx.x * blockDim.x + threadIdx.x) >> 5;
    int lane = threadIdx.x & 31;
    if (warp >= T_TOK) return;

    const float* xr = x + (size_t)warp * D_DIM;
    float l0 = 0.f, l1 = 0.f, l2 = 0.f, l3 = 0.f;
    for (int j = lane; j < D_DIM; j += 32) {
        float xv = xr[j];
        float4 gw = *(const float4*)(gate_w + (size_t)j * 4);
        l0 += xv * gw.x; l1 += xv * gw.y; l2 += xv * gw.z; l3 += xv * gw.w;
    }
#pragma unroll
    for (int off = 16; off; off >>= 1) {
        l0 += __shfl_down_sync(0xffffffffu, l0, off);
        l1 += __shfl_down_sync(0xffffffffu, l1, off);
        l2 += __shfl_down_sync(0xffffffffu, l2, off);
        l3 += __shfl_down_sync(0xffffffffu, l3, off);
    }
    if (lane != 0) return;

    float ent = ((g_entp[0][warp] + g_entp[1][warp]) +
                 (g_entp[2][warp] + g_entp[3][warp])) + dp_b2[0];
    ent = fmaxf(ent, 0.f) + log1pf(expf(-fabsf(ent)));
    float norm = fminf(fmaxf((ent - 0.5f) / 1.5f, 0.f), 1.f);
    int k = (int)rintf(1.0f + norm * 3.0f);
    k = max(1, min(E_EXP, k));

    float lg[4] = { l0 + gate_b[0], l1 + gate_b[1], l2 + gate_b[2], l3 + gate_b[3] };
    int idx[4] = { 0, 1, 2, 3 };
#pragma unroll
    for (int a = 0; a < 3; a++) {
        int best = a;
#pragma unroll
        for (int b = a + 1; b < 4; b++)
            if (lg[idx[b]] > lg[idx[best]]) best = b;
        int t = idx[a]; idx[a] = idx[best]; idx[best] = t;
    }
    float mx = lg[idx[0]];
    float w[4]; float wsum = 0.f;
#pragma unroll
    for (int j = 0; j < 4; j++) {
        w[j] = (j < k) ? expf(lg[idx[j]] - mx) : 0.f;
        wsum += w[j];
    }
    float inv = 1.f / wsum;
    float dw[4] = { 0.f, 0.f, 0.f, 0.f };
#pragma unroll
    for (int j = 0; j < 4; j++)
        if (j < k) dw[idx[j]] = w[j] * inv;
#pragma unroll
    for (int e2 = 0; e2 < 4; e2++) g_dw[(size_t)warp * 4 + e2] = dw[e2];

    for (int j = 0; j < k; j++) {
        int ex = idx[j];
        int p = atomicAdd(&g_cnt[ex], 1);
        g_list[(size_t)ex * T_TOK + p] = warp;
    }
}

// ---------------- combine (k>1 tokens only) ----------------------------------
__global__ void combine_kernel(float* __restrict__ out)
{
    const size_t P = (size_t)T_TOK * D_DIM / 4;
    size_t i = (size_t)blockIdx.x * blockDim.x + threadIdx.x;
    if (i >= P) return;
    int t = (int)(i >> 8);
    float w0 = g_dw[(size_t)t * 4 + 0];
    float w1 = g_dw[(size_t)t * 4 + 1];
    float w2 = g_dw[(size_t)t * 4 + 2];
    float w3 = g_dw[(size_t)t * 4 + 3];
    // k=1 tokens (weight exactly 1.0) were written directly by mgemm2
    if (w0 == 1.f || w1 == 1.f || w2 == 1.f || w3 == 1.f) return;
    const float4* y4 = (const float4*)g_y;
    float4 o = make_float4(0.f, 0.f, 0.f, 0.f);
    if (w0 != 0.f) { float4 a = y4[i];
        o.x += w0 * a.x; o.y += w0 * a.y; o.z += w0 * a.z; o.w += w0 * a.w; }
    if (w1 != 0.f) { float4 a = y4[P + i];
        o.x += w1 * a.x; o.y += w1 * a.y; o.z += w1 * a.z; o.w += w1 * a.w; }
    if (w2 != 0.f) { float4 a = y4[2 * P + i];
        o.x += w2 * a.x; o.y += w2 * a.y; o.z += w2 * a.z; o.w += w2 * a.w; }
    if (w3 != 0.f) { float4 a = y4[3 * P + i];
        o.x += w3 * a.x; o.y += w3 * a.y; o.z += w3 * a.z; o.w += w3 * a.w; }
    ((float4*)out)[i] = o;
}

// ---------------- launch -----------------------------------------------------
extern "C" void kernel_launch(void* const* d_in, const int* in_sizes, int n_in,
                              void* d_out, int out_size)
{
    (void)in_sizes; (void)n_in; (void)out_size;
    const float* x      = (const float*)d_in[0];
    const float* gate_w = (const float*)d_in[1];
    const float* gate_b = (const float*)d_in[2];
    const float* dp_w1  = (const float*)d_in[3];
    const float* dp_b1  = (const float*)d_in[4];
    const float* dp_w2  = (const float*)d_in[5];
    const float* dp_b2  = (const float*)d_in[6];
    const float* ew1    = (const float*)d_in[7];
    const float* eb1    = (const float*)d_in[8];
    const float* ew2    = (const float*)d_in[9];
    const float* eb2    = (const float*)d_in[10];
    float* out = (float*)d_out;

    void *p_xh, *p_xlo, *p_hidh, *p_y, *p_w1t, *p_w2t, *p_dwhi, *p_dwlo;
    cudaGetSymbolAddress(&p_xh,   g_xh);
    cudaGetSymbolAddress(&p_xlo,  g_xlo);
    cudaGetSymbolAddress(&p_hidh, g_hidh);
    cudaGetSymbolAddress(&p_y,    g_y);
    cudaGetSymbolAddress(&p_w1t,  g_w1t);
    cudaGetSymbolAddress(&p_w2t,  g_w2t);
    cudaGetSymbolAddress(&p_dwhi, g_dwhi);
    cudaGetSymbolAddress(&p_dwlo, g_dwlo);
    __half* sxh  = (__half*)p_xh;
    __half* sxlo = (__half*)p_xlo;
    __half* shid = (__half*)p_hidh;
    float*  sy   = (float*)p_y;
    __half* w1t  = (__half*)p_w1t;
    __half* w2t  = (__half*)p_w2t;
    __half* dwhi = (__half*)p_dwhi;
    __half* dwlo = (__half*)p_dwlo;

    cudaFuncSetAttribute(mgemm_h<true, false, true, true, false>,
                         cudaFuncAttributeMaxDynamicSharedMemorySize, HSM_TOTAL);
    cudaFuncSetAttribute(mgemm_h<false, true, false, false, true>,
                         cudaFuncAttributeMaxDynamicSharedMemorySize, HSM_TOTAL);
    cudaFuncSetAttribute(dptc_k,
                         cudaFuncAttributeMaxDynamicSharedMemorySize, DP_TOTAL);

    // 1. zero expert counters
    init_kernel<<<1, 32>>>();

    // 2. x -> fp16 hi/lo; weight transposes
    xsplit_k<<<(T_TOK * D_DIM / 4) / 256, 256>>>(x, sxh, sxlo);
    transpose_hl_k<<<dim3(DP_H / 32, D_DIM / 32, 1), dim3(32, 8)>>>(dp_w1, dwhi, dwlo, D_DIM, DP_H);
    transpose_k<<<dim3(H_DIM / 32, D_DIM / 32, E_EXP), dim3(32, 8)>>>(ew1, w1t, D_DIM, H_DIM);
    transpose_k<<<dim3(D_DIM / 32, H_DIM / 32, E_EXP), dim3(32, 8)>>>(ew2, w2t, H_DIM, D_DIM);

    // 3. dp GEMM on tensor cores (fp16x3 split, R7 256-thr config) + entropy
    dptc_k<<<dim3(T_TOK / 128, DP_H / 128), 256, DP_TOTAL>>>(
        sxh, sxlo, dwhi, dwlo, dp_b1, dp_w2);

    // 4. routing (exact fp32 logits + deterministic entropy partial sum)
    route_kernel<<<(T_TOK * 32) / 256, 256>>>(x, dp_b2, gate_w, gate_b);

    // 5. expert GEMM1 (fp16 mma, gathered A): hid = relu(Xh[list] @ W1 + b1) -> fp16
    mgemm_h<true, false, true, true, false><<<dim3(T_TOK / 128, H_DIM / 256, E_EXP), 512, HSM_TOTAL>>>(
        sxh, 0, D_DIM, w1t, (size_t)D_DIM * H_DIM, eb1, H_DIM,
        shid, (size_t)T_TOK * H_DIM, H_DIM, D_DIM, nullptr);

    // 6. expert GEMM2 (fp16 mma, scattered C, k=1 rows straight to out)
    mgemm_h<false, true, false, false, true><<<dim3(T_TOK / 128, D_DIM / 256, E_EXP), 512, HSM_TOTAL>>>(
        shid, (size_t)T_TOK * H_DIM, H_DIM, w2t, (size_t)H_DIM * D_DIM, eb2, D_DIM,
        sy, (size_t)T_TOK * D_DIM, D_DIM, H_DIM, out);

    // 7. weighted combine (k>1 tokens only)
    combine_kernel<<<(T_TOK * D_DIM / 4) / 256, 256>>>(out);
}